// round 7
// baseline (speedup 1.0000x reference)
#include <cuda_runtime.h>
#include <cuda_bf16.h>
#include <math.h>
#include <stdint.h>

// ---------------------------------------------------------------------------
// Problem constants
// ---------------------------------------------------------------------------
#define BATCH   32
#define NTOK    255
#define NTOT    256
#define DIN     64
#define NHEAD   12
#define HID     768
#define FFN     3072
#define NLAYER  6
#define HDIM    64
#define MROWS   (BATCH*NTOT) // 8192
#define MATOM   (BATCH*NTOK) // 8160

// ---------------------------------------------------------------------------
// Scratch (device globals; no allocations allowed)
// ---------------------------------------------------------------------------
__device__ __align__(256) float g_h  [(size_t)MROWS*HID];
__device__ __align__(256) float g_y  [(size_t)MROWS*HID];
__device__ __align__(256) float g_q  [(size_t)MROWS*HID];
__device__ __align__(256) float g_k  [(size_t)MROWS*HID];
__device__ __align__(256) float g_v  [(size_t)MROWS*HID];
__device__ __align__(256) float g_o  [(size_t)MROWS*HID];
__device__ __align__(256) float g_f  [(size_t)MROWS*FFN];
__device__ __align__(256) float g_bias[(size_t)BATCH*NHEAD*NTOT*NTOT];

// fragment-packed tf32 weights, per layer: Wq,Wk,Wv,Wo ([768*768] each),
// W1 ([768*3072]), W2 ([3072*768])
#define WT_QKVO (HID*HID)
#define WT_L    (4*WT_QKVO + 2*HID*FFN)
__device__ __align__(256) unsigned g_wt[(size_t)NLAYER*WT_L];

enum { EP_BIAS = 0, EP_BIAS_RES = 1, EP_BIAS_GELU = 2 };

// ---------------------------------------------------------------------------
// helpers
// ---------------------------------------------------------------------------
__device__ __forceinline__ unsigned f2tf32(float f) {
    unsigned u;
    asm("cvt.rna.tf32.f32 %0, %1;" : "=r"(u) : "f"(f));
    return u;
}
__device__ __forceinline__ void cp16(void* smem, const void* gmem) {
    unsigned s = (unsigned)__cvta_generic_to_shared(smem);
    asm volatile("cp.async.cg.shared.global [%0], [%1], 16;" :: "r"(s), "l"(gmem));
}
__device__ __forceinline__ void mma16n8k8(float c[4], const unsigned a[4],
                                          const unsigned b[2]) {
    asm volatile(
        "mma.sync.aligned.m16n8k8.row.col.f32.tf32.tf32.f32 "
        "{%0,%1,%2,%3}, {%4,%5,%6,%7}, {%8,%9}, {%0,%1,%2,%3};"
        : "+f"(c[0]), "+f"(c[1]), "+f"(c[2]), "+f"(c[3])
        : "r"(a[0]), "r"(a[1]), "r"(a[2]), "r"(a[3]), "r"(b[0]), "r"(b[1]));
}

// ---------------------------------------------------------------------------
// Weight repack: W[K][N] fp32 -> fragment-ordered tf32.
// Packed layout per (ntile of 128, ktile of 16):
//   idx = ((nt*(K/16)+kt)*2048) + (k8*8 + jpb)*128 + lane*4 + c
//   value = W[kt*16 + k8*8 + q + (c&1)*4][nt*128 + jpb*16 + (c>>1)*8 + g]
//   (g = lane>>2, q = lane&3)
// ---------------------------------------------------------------------------
__global__ __launch_bounds__(256) void repack_kernel(
    const float* __restrict__ in, unsigned* __restrict__ out,
    int K, int N, int ktiles, size_t inStride, size_t outStride)
{
    in  += (size_t)blockIdx.z * inStride;
    out += (size_t)blockIdx.z * outStride;
    const unsigned idx = blockIdx.x * 256u + threadIdx.x;
    const int c    = idx & 3;
    const int lane = (idx >> 2) & 31;
    const int jpb  = (idx >> 7) & 7;
    const int k8   = (idx >> 10) & 1;
    const unsigned rest = idx >> 11;
    const int kt = (int)(rest % (unsigned)ktiles);
    const int nt = (int)(rest / (unsigned)ktiles);
    const int g = lane >> 2, q = lane & 3;
    const int k = kt * 16 + k8 * 8 + q + (c & 1) * 4;
    const int n = nt * 128 + jpb * 16 + ((c >> 1) & 1) * 8 + g;
    out[idx] = f2tf32(in[(size_t)k * N + n]);
}

// ---------------------------------------------------------------------------
// TF32 mma.sync GEMM with fragment-ordered operands.
// CTA 128x128, 256 thr (8 warps, 4xM 2xN, warp tile 32x64), K-chunk 16,
// cp.async double buffer. B comes pre-packed from gmem (zero repack);
// A staged raw fp32 then repacked to fragment-major tf32 in smem.
// smem: stageA 2*128*20 f32 (20480B) | fragA 2*2048 u32 (16384B) | fragB same.
// ---------------------------------------------------------------------------
#define TG_SMEM 53248

template<int MODE>
__global__ __launch_bounds__(256, 2) void tgemm_kernel(
    const float* __restrict__ A, const unsigned* __restrict__ Wpk,
    const float* __restrict__ bias, const float* __restrict__ R,
    float* __restrict__ C, int K, int N)
{
    extern __shared__ float smdyn[];
    float*    stageA = smdyn;                          // 2 * 2560 floats
    unsigned* fragA  = (unsigned*)(smdyn + 5120);      // 2 * 2048
    unsigned* fragB  = fragA + 4096;                   // 2 * 2048

    const int tid  = threadIdx.x;
    const int lane = tid & 31;
    const int warp = tid >> 5;
    const int g    = lane >> 2;
    const int q    = lane & 3;
    const int bm0  = blockIdx.y * 128;
    const int bn0  = blockIdx.x * 128;
    const int wn   = (warp & 1) * 64;
    const int wm   = (warp >> 1) * 32;

    const int nc = K / 16;
    const float* Ag = A + (size_t)(bm0 + (tid >> 1)) * K + (tid & 1) * 8;
    const unsigned* Bg = Wpk + (size_t)blockIdx.x * nc * 2048 + tid * 8;
    float* sa0 = stageA + (tid >> 1) * 20 + (tid & 1) * 8;

    float acc[2][8][4];
    #pragma unroll
    for (int t = 0; t < 2; t++)
        #pragma unroll
        for (int j = 0; j < 8; j++)
            #pragma unroll
            for (int r = 0; r < 4; r++) acc[t][j][r] = 0.f;

    auto issue = [&](int b, int kt) {
        const float* ag = Ag + kt * 16;
        float* sa = sa0 + b * 2560;
        cp16(sa,     ag);
        cp16(sa + 4, ag + 4);
        const unsigned* bg = Bg + (size_t)kt * 2048;
        unsigned* fb = fragB + b * 2048 + tid * 8;
        cp16(fb,     bg);
        cp16(fb + 4, bg + 4);
        asm volatile("cp.async.commit_group;");
    };

    issue(0, 0);

    for (int c = 0; c < nc; c++) {
        const int buf = c & 1;
        const bool more = (c + 1) < nc;
        if (more) issue(buf ^ 1, c + 1);
        if (more) asm volatile("cp.async.wait_group 1;");
        else      asm volatile("cp.async.wait_group 0;");
        __syncthreads();

        // repack A: stage (fp32, stride 20) -> fragA (tf32, fragment-major)
        #pragma unroll
        for (int r = 0; r < 2; r++) {
            const int fl = tid + r * 256;           // fragment-lane id 0..511
            const int ln = fl & 31, fb = fl >> 5;   // fb = mb*2 + k8
            const int mb = fb >> 1, k8 = fb & 1;
            const int gg = ln >> 2, qq = ln & 3;
            const float* st = stageA + buf * 2560 + (mb * 16 + gg) * 20 + k8 * 8 + qq;
            uint4 w;
            w.x = f2tf32(st[0]);
            w.y = f2tf32(st[160]);       // +8 rows * 20
            w.z = f2tf32(st[4]);
            w.w = f2tf32(st[164]);
            *reinterpret_cast<uint4*>(fragA + buf * 2048 + fl * 4) = w;
        }
        __syncthreads();

        // consume
        const unsigned* fA = fragA + buf * 2048;
        const unsigned* fB = fragB + buf * 2048;
        #pragma unroll
        for (int k8 = 0; k8 < 2; k8++) {
            unsigned af[2][4];
            #pragma unroll
            for (int t = 0; t < 2; t++) {
                const int fb = ((warp >> 1) * 2 + t) * 2 + k8;
                const uint4 v = *reinterpret_cast<const uint4*>(fA + fb * 128 + lane * 4);
                af[t][0] = v.x; af[t][1] = v.y; af[t][2] = v.z; af[t][3] = v.w;
            }
            #pragma unroll
            for (int jp = 0; jp < 4; jp++) {
                const int jpb = (warp & 1) * 4 + jp;
                const uint4 v = *reinterpret_cast<const uint4*>(
                    fB + (k8 * 8 + jpb) * 128 + lane * 4);
                unsigned b0[2] = { v.x, v.y };
                unsigned b1[2] = { v.z, v.w };
                mma16n8k8(acc[0][jp * 2    ], af[0], b0);
                mma16n8k8(acc[0][jp * 2 + 1], af[0], b1);
                mma16n8k8(acc[1][jp * 2    ], af[1], b0);
                mma16n8k8(acc[1][jp * 2 + 1], af[1], b1);
            }
        }
        __syncthreads();
    }

    // epilogue
    #pragma unroll
    for (int t = 0; t < 2; t++) {
        const int m0 = bm0 + wm + t * 16 + g;
        const int m1 = m0 + 8;
        #pragma unroll
        for (int j = 0; j < 8; j++) {
            const int n0 = bn0 + wn + j * 8 + q * 2;
            const float b0 = bias[n0], b1 = bias[n0 + 1];
            float v00 = acc[t][j][0] + b0;
            float v01 = acc[t][j][1] + b1;
            float v10 = acc[t][j][2] + b0;
            float v11 = acc[t][j][3] + b1;
            if (MODE == EP_BIAS_GELU) {
                v00 = 0.5f * v00 * (1.f + erff(v00 * 0.70710678118654752f));
                v01 = 0.5f * v01 * (1.f + erff(v01 * 0.70710678118654752f));
                v10 = 0.5f * v10 * (1.f + erff(v10 * 0.70710678118654752f));
                v11 = 0.5f * v11 * (1.f + erff(v11 * 0.70710678118654752f));
            }
            if (MODE == EP_BIAS_RES) {
                const float2 r0 = *reinterpret_cast<const float2*>(R + (size_t)m0 * N + n0);
                const float2 r1 = *reinterpret_cast<const float2*>(R + (size_t)m1 * N + n0);
                v00 += r0.x; v01 += r0.y; v10 += r1.x; v11 += r1.y;
            }
            *reinterpret_cast<float2*>(C + (size_t)m0 * N + n0) = make_float2(v00, v01);
            *reinterpret_cast<float2*>(C + (size_t)m1 * N + n0) = make_float2(v10, v11);
        }
    }
}

// ---------------------------------------------------------------------------
// fp32 SGEMM (atom-encoder only: K=64, row remap)
// ---------------------------------------------------------------------------
#define BM 128
#define BN 128
#define BK 8
#define TM 8
#define TN 8

template<int MODE, bool REMAP>
__global__ __launch_bounds__(256) void sgemm_kernel(
    const float* __restrict__ A, const float* __restrict__ W,
    const float* __restrict__ bias, const float* __restrict__ R,
    float* __restrict__ C, int M, int K, int N)
{
    __shared__ float As[BK][BM];
    __shared__ float Bs[BK][BN];

    const int tid = threadIdx.x;
    const int bm0 = blockIdx.y * BM;
    const int bn0 = blockIdx.x * BN;
    const int tx = tid & 15;
    const int ty = tid >> 4;

    float acc[TM][TN];
    #pragma unroll
    for (int i = 0; i < TM; i++)
        #pragma unroll
        for (int j = 0; j < TN; j++) acc[i][j] = 0.f;

    const int arow = tid >> 1;
    const int acol = (tid & 1) * 4;
    const int brow = tid >> 5;
    const int bcol = (tid & 31) * 4;

    for (int k0 = 0; k0 < K; k0 += BK) {
        float4 av;
        const int gm = bm0 + arow;
        if (gm < M)
            av = *reinterpret_cast<const float4*>(A + (size_t)gm * K + k0 + acol);
        else
            av = make_float4(0.f, 0.f, 0.f, 0.f);
        As[acol + 0][arow] = av.x;
        As[acol + 1][arow] = av.y;
        As[acol + 2][arow] = av.z;
        As[acol + 3][arow] = av.w;

        const float4 bv = *reinterpret_cast<const float4*>(
            W + (size_t)(k0 + brow) * N + bn0 + bcol);
        *reinterpret_cast<float4*>(&Bs[brow][bcol]) = bv;

        __syncthreads();
        #pragma unroll
        for (int k = 0; k < BK; k++) {
            float af[TM], bf[TN];
            #pragma unroll
            for (int i = 0; i < TM; i++) af[i] = As[k][ty * TM + i];
            #pragma unroll
            for (int j = 0; j < TN; j++) bf[j] = Bs[k][tx * TN + j];
            #pragma unroll
            for (int i = 0; i < TM; i++)
                #pragma unroll
                for (int j = 0; j < TN; j++)
                    acc[i][j] = fmaf(af[i], bf[j], acc[i][j]);
        }
        __syncthreads();
    }

    #pragma unroll
    for (int i = 0; i < TM; i++) {
        const int m = bm0 + ty * TM + i;
        if (m >= M) continue;
        size_t orow;
        if (REMAP) orow = (size_t)m + (size_t)(m / NTOK) * 1 + 1;
        else       orow = (size_t)m;
        #pragma unroll
        for (int j = 0; j < TN; j++) {
            const int nn = bn0 + tx * TN + j;
            float v = acc[i][j] + bias[nn];
            if (MODE == EP_BIAS_GELU)
                v = 0.5f * v * (1.f + erff(v * 0.70710678118654752f));
            if (MODE == EP_BIAS_RES)
                v += R[orow * N + nn];
            C[orow * N + nn] = v;
        }
    }
}

// ---------------------------------------------------------------------------
// graph-token fill
// ---------------------------------------------------------------------------
__global__ void fill_token_kernel(const float* __restrict__ gt, float* __restrict__ h)
{
    h[(size_t)blockIdx.x * NTOT * HID + threadIdx.x] = gt[threadIdx.x];
}

// ---------------------------------------------------------------------------
// Structural bias precompute
// ---------------------------------------------------------------------------
__global__ void bias_kernel(const int* __restrict__ len_spd,
                            const float* __restrict__ spd_emb,
                            const float* __restrict__ virt,
                            float* __restrict__ bias)
{
    const size_t idx = (size_t)blockIdx.x * blockDim.x + threadIdx.x;
    const size_t total = (size_t)BATCH * NHEAD * NTOT * NTOT;
    if (idx >= total) return;
    const int j = (int)(idx & 255);
    const int i = (int)((idx >> 8) & 255);
    const int h = (int)((idx >> 16) % NHEAD);
    const int b = (int)(idx / ((size_t)NHEAD * NTOT * NTOT));
    float v;
    if (i == 0 || j == 0) {
        v = virt[h];
    } else {
        const int lsp = len_spd[((size_t)b * NTOK + (i - 1)) * NTOK + (j - 1)];
        v = (lsp == 0) ? 0.f : spd_emb[lsp * NHEAD + h];
    }
    bias[idx] = v;
}

// ---------------------------------------------------------------------------
// LayerNorm
// ---------------------------------------------------------------------------
__global__ __launch_bounds__(256) void ln_kernel(
    const float* __restrict__ X, const float* __restrict__ w,
    const float* __restrict__ b, float* __restrict__ Y)
{
    const int row = blockIdx.x;
    const float* x = X + (size_t)row * HID;
    float* y = Y + (size_t)row * HID;
    const int tid = threadIdx.x;

    float v0 = x[tid], v1 = x[tid + 256], v2 = x[tid + 512];
    float s = v0 + v1 + v2;

    __shared__ float red[8];
    #pragma unroll
    for (int o = 16; o > 0; o >>= 1) s += __shfl_xor_sync(~0u, s, o);
    if ((tid & 31) == 0) red[tid >> 5] = s;
    __syncthreads();
    float tot = red[0];
    #pragma unroll
    for (int wv = 1; wv < 8; wv++) tot += red[wv];
    const float mu = tot * (1.f / HID);
    __syncthreads();

    const float d0 = v0 - mu, d1 = v1 - mu, d2 = v2 - mu;
    float s2 = d0 * d0 + d1 * d1 + d2 * d2;
    #pragma unroll
    for (int o = 16; o > 0; o >>= 1) s2 += __shfl_xor_sync(~0u, s2, o);
    if ((tid & 31) == 0) red[tid >> 5] = s2;
    __syncthreads();
    float var = red[0];
    #pragma unroll
    for (int wv = 1; wv < 8; wv++) var += red[wv];
    var *= (1.f / HID);
    const float inv = rsqrtf(var + 1e-5f);

    y[tid]       = d0 * inv * w[tid]       + b[tid];
    y[tid + 256] = d1 * inv * w[tid + 256] + b[tid + 256];
    y[tid + 512] = d2 * inv * w[tid + 512] + b[tid + 512];
}

// ---------------------------------------------------------------------------
// Attention (unchanged this round)
// ---------------------------------------------------------------------------
#define KVSTRIDE 65
#define ATTN_SMEM ((2 * 256 * KVSTRIDE + 64 + 256 + 256 + 16) * sizeof(float))

__global__ __launch_bounds__(256) void attn_kernel(
    const float* __restrict__ Q, const float* __restrict__ K,
    const float* __restrict__ V, const float* __restrict__ bias,
    float* __restrict__ O)
{
    extern __shared__ float sm[];
    float* Ks   = sm;
    float* Vs   = Ks + 256 * KVSTRIDE;
    float* qs   = Vs + 256 * KVSTRIDE;
    float* pp   = qs + 64;
    float* part = pp + 256;
    float* redm = part + 256;
    float* reds = redm + 8;

    const int h = blockIdx.x;
    const int b = blockIdx.y;
    const int tid = threadIdx.x;
    const int lane = tid & 31;
    const int warp = tid >> 5;

    const size_t base = (size_t)b * NTOT * HID + (size_t)h * HDIM;

    for (int idx = tid; idx < 256 * 64; idx += 256) {
        const int j = idx >> 6, dd = idx & 63;
        Ks[j * KVSTRIDE + dd] = K[base + (size_t)j * HID + dd];
        Vs[j * KVSTRIDE + dd] = V[base + (size_t)j * HID + dd];
    }
    __syncthreads();

    const float* brow = bias + (((size_t)b * NHEAD + h) * NTOT) * NTOT;

    for (int i = 0; i < NTOT; i++) {
        if (tid < 64) qs[tid] = Q[base + (size_t)i * HID + tid];
        __syncthreads();

        float s = 0.f;
        const float* kr = &Ks[tid * KVSTRIDE];
        #pragma unroll 16
        for (int dd = 0; dd < 64; dd++) s = fmaf(qs[dd], kr[dd], s);
        s = s * 0.125f + brow[(size_t)i * NTOT + tid];

        float m = s;
        #pragma unroll
        for (int o = 16; o > 0; o >>= 1) m = fmaxf(m, __shfl_xor_sync(~0u, m, o));
        if (lane == 0) redm[warp] = m;
        __syncthreads();
        float mall = redm[0];
        #pragma unroll
        for (int wv = 1; wv < 8; wv++) mall = fmaxf(mall, redm[wv]);

        const float e = expf(s - mall);
        pp[tid] = e;
        float se = e;
        #pragma unroll
        for (int o = 16; o > 0; o >>= 1) se += __shfl_xor_sync(~0u, se, o);
        if (lane == 0) reds[warp] = se;
        __syncthreads();
        float sum = reds[0];
        #pragma unroll
        for (int wv = 1; wv < 8; wv++) sum += reds[wv];
        const float invsum = 1.f / sum;

        const int gg = tid >> 6, dd = tid & 63;
        float acc = 0.f;
        #pragma unroll 16
        for (int jj = 0; jj < 64; jj++) {
            const int jr = gg * 64 + jj;
            acc = fmaf(pp[jr], Vs[jr * KVSTRIDE + dd], acc);
        }
        part[tid] = acc;
        __syncthreads();

        if (tid < 64) {
            const float o4 = (part[tid] + part[64 + tid] + part[128 + tid] + part[192 + tid]) * invsum;
            O[base + (size_t)i * HID + tid] = o4;
        }
        __syncthreads();
    }
}

// ---------------------------------------------------------------------------
// Launch
// ---------------------------------------------------------------------------
extern "C" void kernel_launch(void* const* d_in, const int* in_sizes, int n_in,
                              void* d_out, int out_size)
{
    const float* x          = (const float*)d_in[0];
    const int*   len_spd    = (const int*)  d_in[1];
    const float* atom_W     = (const float*)d_in[2];
    const float* atom_b     = (const float*)d_in[3];
    const float* spd_emb    = (const float*)d_in[4];
    const float* graph_tok  = (const float*)d_in[5];
    const float* virt_dist  = (const float*)d_in[6];
    const float* ln1_w      = (const float*)d_in[7];
    const float* ln1_b      = (const float*)d_in[8];
    const float* Wq         = (const float*)d_in[9];
    const float* bq         = (const float*)d_in[10];
    const float* Wk         = (const float*)d_in[11];
    const float* bk         = (const float*)d_in[12];
    const float* Wv         = (const float*)d_in[13];
    const float* bv         = (const float*)d_in[14];
    const float* Wo         = (const float*)d_in[15];
    const float* bo         = (const float*)d_in[16];
    const float* ln2_w      = (const float*)d_in[17];
    const float* ln2_b      = (const float*)d_in[18];
    const float* W1         = (const float*)d_in[19];
    const float* b1         = (const float*)d_in[20];
    const float* W2         = (const float*)d_in[21];
    const float* b2         = (const float*)d_in[22];
    const float* fln_w      = (const float*)d_in[23];
    const float* fln_b      = (const float*)d_in[24];

    float *h, *y, *q, *k, *v, *o, *f, *bias;
    unsigned* wt;
    cudaGetSymbolAddress((void**)&h,    g_h);
    cudaGetSymbolAddress((void**)&y,    g_y);
    cudaGetSymbolAddress((void**)&q,    g_q);
    cudaGetSymbolAddress((void**)&k,    g_k);
    cudaGetSymbolAddress((void**)&v,    g_v);
    cudaGetSymbolAddress((void**)&o,    g_o);
    cudaGetSymbolAddress((void**)&f,    g_f);
    cudaGetSymbolAddress((void**)&bias, g_bias);
    cudaGetSymbolAddress((void**)&wt,   g_wt);

    cudaFuncSetAttribute(attn_kernel, cudaFuncAttributeMaxDynamicSharedMemorySize,
                         (int)ATTN_SMEM);
    cudaFuncSetAttribute(tgemm_kernel<EP_BIAS>,
                         cudaFuncAttributeMaxDynamicSharedMemorySize, TG_SMEM);
    cudaFuncSetAttribute(tgemm_kernel<EP_BIAS_RES>,
                         cudaFuncAttributeMaxDynamicSharedMemorySize, TG_SMEM);
    cudaFuncSetAttribute(tgemm_kernel<EP_BIAS_GELU>,
                         cudaFuncAttributeMaxDynamicSharedMemorySize, TG_SMEM);

    // 0) weight repack into fragment order (tf32)
    {
        const size_t szQ = (size_t)HID * HID, szF = (size_t)HID * FFN;
        dim3 gq((unsigned)(szQ / 256), 1, NLAYER);
        repack_kernel<<<gq, 256>>>(Wq, wt + 0 * WT_QKVO, HID, HID, HID / 16, szQ, (size_t)WT_L);
        repack_kernel<<<gq, 256>>>(Wk, wt + 1 * WT_QKVO, HID, HID, HID / 16, szQ, (size_t)WT_L);
        repack_kernel<<<gq, 256>>>(Wv, wt + 2 * WT_QKVO, HID, HID, HID / 16, szQ, (size_t)WT_L);
        repack_kernel<<<gq, 256>>>(Wo, wt + 3 * WT_QKVO, HID, HID, HID / 16, szQ, (size_t)WT_L);
        dim3 gf((unsigned)(szF / 256), 1, NLAYER);
        repack_kernel<<<gf, 256>>>(W1, wt + 4 * WT_QKVO, HID, FFN, HID / 16, szF, (size_t)WT_L);
        repack_kernel<<<gf, 256>>>(W2, wt + 4 * WT_QKVO + szF, FFN, HID, FFN / 16, szF, (size_t)WT_L);
    }

    // 1) atom encoder (fp32, K=64, remapped rows)
    {
        dim3 grid(HID / BN, (MATOM + BM - 1) / BM);
        sgemm_kernel<EP_BIAS, true><<<grid, 256>>>(x, atom_W, atom_b, nullptr, h,
                                                   MATOM, DIN, HID);
    }
    // 2) graph token row 0 per batch
    fill_token_kernel<<<BATCH, HID>>>(graph_tok, h);

    // 3) structural bias (once)
    {
        const size_t total = (size_t)BATCH * NHEAD * NTOT * NTOT;
        bias_kernel<<<(unsigned)((total + 255) / 256), 256>>>(len_spd, spd_emb,
                                                              virt_dist, bias);
    }

    const dim3 gHID(HID / 128, MROWS / 128);   // 6 x 64
    const dim3 gFFN(FFN / 128, MROWS / 128);   // 24 x 64

    for (int l = 0; l < NLAYER; l++) {
        const size_t bofs  = (size_t)l * HID;
        const size_t b1ofs = (size_t)l * FFN;
        unsigned* wl = wt + (size_t)l * WT_L;
        const size_t szF = (size_t)HID * FFN;

        ln_kernel<<<MROWS, 256>>>(h, ln1_w + bofs, ln1_b + bofs, y);

        tgemm_kernel<EP_BIAS><<<gHID, 256, TG_SMEM>>>(
            y, wl + 0 * WT_QKVO, bq + bofs, nullptr, q, HID, HID);
        tgemm_kernel<EP_BIAS><<<gHID, 256, TG_SMEM>>>(
            y, wl + 1 * WT_QKVO, bk + bofs, nullptr, k, HID, HID);
        tgemm_kernel<EP_BIAS><<<gHID, 256, TG_SMEM>>>(
            y, wl + 2 * WT_QKVO, bv + bofs, nullptr, v, HID, HID);

        attn_kernel<<<dim3(NHEAD, BATCH), 256, ATTN_SMEM>>>(q, k, v, bias, o);

        tgemm_kernel<EP_BIAS_RES><<<gHID, 256, TG_SMEM>>>(
            o, wl + 3 * WT_QKVO, bo + bofs, h, h, HID, HID);

        ln_kernel<<<MROWS, 256>>>(h, ln2_w + bofs, ln2_b + bofs, y);

        tgemm_kernel<EP_BIAS_GELU><<<gFFN, 256, TG_SMEM>>>(
            y, wl + 4 * WT_QKVO, b1 + b1ofs, nullptr, f, HID, FFN);
        tgemm_kernel<EP_BIAS_RES><<<gHID, 256, TG_SMEM>>>(
            f, wl + 4 * WT_QKVO + szF, b2 + bofs, h, h, FFN, HID);
    }

    ln_kernel<<<MROWS, 256>>>(h, fln_w, fln_b, (float*)d_out);
}

// round 8
// speedup vs baseline: 1.2561x; 1.2561x over previous
#include <cuda_runtime.h>
#include <cuda_fp16.h>
#include <math.h>
#include <stdint.h>

// ---------------------------------------------------------------------------
// Problem constants
// ---------------------------------------------------------------------------
#define BATCH   32
#define NTOK    255
#define NTOT    256
#define DIN     64
#define NHEAD   12
#define HID     768
#define FFN     3072
#define NLAYER  6
#define HDIM    64
#define MROWS   (BATCH*NTOT) // 8192
#define MATOM   (BATCH*NTOK) // 8160

// ---------------------------------------------------------------------------
// Scratch (device globals; no allocations allowed)
// ---------------------------------------------------------------------------
__device__ __align__(256) float  g_h  [(size_t)MROWS*HID];
__device__ __align__(256) float  g_q  [(size_t)MROWS*HID];
__device__ __align__(256) float  g_k  [(size_t)MROWS*HID];
__device__ __align__(256) float  g_v  [(size_t)MROWS*HID];
__device__ __align__(256) __half g_yh [(size_t)MROWS*HID];
__device__ __align__(256) __half g_oh [(size_t)MROWS*HID];
__device__ __align__(256) __half g_fh [(size_t)MROWS*FFN];
__device__ __align__(256) float  g_bias[(size_t)BATCH*NHEAD*NTOT*NTOT];

// fragment-packed fp16 weights (per layer: Wq,Wk,Wv,Wo,W1,W2)
#define WT_QKVO (HID*HID)                  // halves
#define WT_L    (4*WT_QKVO + 2*HID*FFN)    // 7077888 halves per layer
__device__ __align__(256) __half g_wt[(size_t)NLAYER*WT_L];

enum { EP_BIAS = 0, EP_BIAS_RES = 1, EP_BIAS_GELU = 2 };

// ---------------------------------------------------------------------------
// helpers
// ---------------------------------------------------------------------------
__device__ __forceinline__ void cp16(void* smem, const void* gmem) {
    unsigned s = (unsigned)__cvta_generic_to_shared(smem);
    asm volatile("cp.async.cg.shared.global [%0], [%1], 16;" :: "r"(s), "l"(gmem));
}
__device__ __forceinline__ void mmah(float c[4], const unsigned a[4],
                                     unsigned b0, unsigned b1) {
    asm volatile(
        "mma.sync.aligned.m16n8k16.row.col.f32.f16.f16.f32 "
        "{%0,%1,%2,%3}, {%4,%5,%6,%7}, {%8,%9}, {%0,%1,%2,%3};"
        : "+f"(c[0]), "+f"(c[1]), "+f"(c[2]), "+f"(c[3])
        : "r"(a[0]), "r"(a[1]), "r"(a[2]), "r"(a[3]), "r"(b0), "r"(b1));
}

// ---------------------------------------------------------------------------
// Weight repack: W[K][N] fp32 -> fragment-ordered fp16 half2.
// half2 idx = ((nt*ktiles + kt)*8 + p)*128 + lane*4 + c
//   khalf = c&1, j = p*2 + (c>>1), g = lane>>2, q = lane&3
//   k = kt*16 + khalf*8 + 2q ; n = nt*128 + j*8 + g
//   value = half2(W[k][n], W[k+1][n])
// ---------------------------------------------------------------------------
__global__ __launch_bounds__(256) void repack_h_kernel(
    const float* __restrict__ in, __half2* __restrict__ out,
    int N, int ktiles, size_t inStride, size_t outStride)
{
    in  += (size_t)blockIdx.z * inStride;
    out += (size_t)blockIdx.z * outStride;
    const unsigned idx = blockIdx.x * 256u + threadIdx.x;
    const int c    = idx & 3;
    const int lane = (idx >> 2) & 31;
    const int p    = (idx >> 7) & 7;
    const unsigned rest = idx >> 10;
    const int kt = (int)(rest % (unsigned)ktiles);
    const int nt = (int)(rest / (unsigned)ktiles);
    const int g = lane >> 2, q = lane & 3;
    const int k = kt * 16 + (c & 1) * 8 + q * 2;
    const int n = nt * 128 + (p * 2 + (c >> 1)) * 8 + g;
    out[idx] = __floats2half2_rn(in[(size_t)k * N + n], in[(size_t)(k + 1) * N + n]);
}

// ---------------------------------------------------------------------------
// fp16 mma.sync GEMM: C[M=8192, N] = epi(A[M,K] @ W + bias (+R))
// A fp16 row-major; W fragment-packed fp16. CTA 128x128, 256 thr
// (8 warps, 4xM 2xN, warp tile 32x64), K-chunk 16, cp.async double buffer.
// stageA stride 24 halves (48B) -> conflict-free LDS.32 fragment loads.
// ---------------------------------------------------------------------------
template<int MODE, bool OUTH>
__global__ __launch_bounds__(256, 2) void hgemm_kernel(
    const __half* __restrict__ A, const __half* __restrict__ Wpk,
    const float* __restrict__ bias, const float* __restrict__ R,
    void* __restrict__ Cout, int K, int N)
{
    __shared__ __half stA[2][128 * 24];   // 12288 B
    __shared__ uint4  fgB[2][256];        // 8192 B

    const int tid  = threadIdx.x;
    const int lane = tid & 31;
    const int warp = tid >> 5;
    const int g    = lane >> 2;
    const int q    = lane & 3;
    const int bm0  = blockIdx.y * 128;
    const int bn0  = blockIdx.x * 128;
    const int wn   = (warp & 1) * 64;
    const int wm   = (warp >> 1) * 32;

    const int nc = K / 16;
    const __half* Ag = A + (size_t)(bm0 + (tid >> 1)) * K + (tid & 1) * 8;
    const uint4*  Bg = reinterpret_cast<const uint4*>(Wpk)
                       + (size_t)blockIdx.x * nc * 256 + tid;
    __half* sa0 = &stA[0][(tid >> 1) * 24 + (tid & 1) * 8];

    float acc[2][8][4];
    #pragma unroll
    for (int t = 0; t < 2; t++)
        #pragma unroll
        for (int j = 0; j < 8; j++)
            #pragma unroll
            for (int r = 0; r < 4; r++) acc[t][j][r] = 0.f;

    auto issue = [&](int b, int kt) {
        cp16(sa0 + b * (128 * 24), Ag + kt * 16);
        cp16(&fgB[b][tid & 255], Bg + (size_t)kt * 256);
        asm volatile("cp.async.commit_group;");
    };

    issue(0, 0);

    for (int c = 0; c < nc; c++) {
        const int buf = c & 1;
        const bool more = (c + 1) < nc;
        if (more) issue(buf ^ 1, c + 1);
        if (more) asm volatile("cp.async.wait_group 1;");
        else      asm volatile("cp.async.wait_group 0;");
        __syncthreads();

        // A fragments: 8 conflict-free LDS.32 per warp
        unsigned a[2][4];
        #pragma unroll
        for (int t = 0; t < 2; t++) {
            const __half* st = &stA[buf][(wm + t * 16 + g) * 24 + 2 * q];
            a[t][0] = *reinterpret_cast<const unsigned*>(st);
            a[t][1] = *reinterpret_cast<const unsigned*>(st + 8 * 24);
            a[t][2] = *reinterpret_cast<const unsigned*>(st + 8);
            a[t][3] = *reinterpret_cast<const unsigned*>(st + 8 * 24 + 8);
        }
        // B fragments + MMA
        #pragma unroll
        for (int jp = 0; jp < 4; jp++) {
            const uint4 v = fgB[buf][((warp & 1) * 4 + jp) * 32 + lane];
            mmah(acc[0][jp * 2    ], a[0], v.x, v.y);
            mmah(acc[0][jp * 2 + 1], a[0], v.z, v.w);
            mmah(acc[1][jp * 2    ], a[1], v.x, v.y);
            mmah(acc[1][jp * 2 + 1], a[1], v.z, v.w);
        }
        __syncthreads();
    }

    // epilogue
    #pragma unroll
    for (int t = 0; t < 2; t++) {
        const int m0 = bm0 + wm + t * 16 + g;
        const int m1 = m0 + 8;
        #pragma unroll
        for (int j = 0; j < 8; j++) {
            const int n0 = bn0 + wn + j * 8 + q * 2;
            const float b0 = bias[n0], b1 = bias[n0 + 1];
            float v00 = acc[t][j][0] + b0;
            float v01 = acc[t][j][1] + b1;
            float v10 = acc[t][j][2] + b0;
            float v11 = acc[t][j][3] + b1;
            if (MODE == EP_BIAS_GELU) {
                v00 = 0.5f * v00 * (1.f + erff(v00 * 0.70710678118654752f));
                v01 = 0.5f * v01 * (1.f + erff(v01 * 0.70710678118654752f));
                v10 = 0.5f * v10 * (1.f + erff(v10 * 0.70710678118654752f));
                v11 = 0.5f * v11 * (1.f + erff(v11 * 0.70710678118654752f));
            }
            if (MODE == EP_BIAS_RES) {
                const float2 r0 = *reinterpret_cast<const float2*>(R + (size_t)m0 * N + n0);
                const float2 r1 = *reinterpret_cast<const float2*>(R + (size_t)m1 * N + n0);
                v00 += r0.x; v01 += r0.y; v10 += r1.x; v11 += r1.y;
            }
            if (OUTH) {
                __half2* C = (__half2*)Cout;
                C[((size_t)m0 * N + n0) >> 1] = __floats2half2_rn(v00, v01);
                C[((size_t)m1 * N + n0) >> 1] = __floats2half2_rn(v10, v11);
            } else {
                float* C = (float*)Cout;
                *reinterpret_cast<float2*>(C + (size_t)m0 * N + n0) = make_float2(v00, v01);
                *reinterpret_cast<float2*>(C + (size_t)m1 * N + n0) = make_float2(v10, v11);
            }
        }
    }
}

// ---------------------------------------------------------------------------
// fp32 SGEMM (atom-encoder only: K=64, row remap)
// ---------------------------------------------------------------------------
#define BM 128
#define BN 128
#define BK 8
#define TM 8
#define TN 8

template<int MODE, bool REMAP>
__global__ __launch_bounds__(256) void sgemm_kernel(
    const float* __restrict__ A, const float* __restrict__ W,
    const float* __restrict__ bias, const float* __restrict__ R,
    float* __restrict__ C, int M, int K, int N)
{
    __shared__ float As[BK][BM];
    __shared__ float Bs[BK][BN];

    const int tid = threadIdx.x;
    const int bm0 = blockIdx.y * BM;
    const int bn0 = blockIdx.x * BN;
    const int tx = tid & 15;
    const int ty = tid >> 4;

    float acc[TM][TN];
    #pragma unroll
    for (int i = 0; i < TM; i++)
        #pragma unroll
        for (int j = 0; j < TN; j++) acc[i][j] = 0.f;

    const int arow = tid >> 1;
    const int acol = (tid & 1) * 4;
    const int brow = tid >> 5;
    const int bcol = (tid & 31) * 4;

    for (int k0 = 0; k0 < K; k0 += BK) {
        float4 av;
        const int gm = bm0 + arow;
        if (gm < M)
            av = *reinterpret_cast<const float4*>(A + (size_t)gm * K + k0 + acol);
        else
            av = make_float4(0.f, 0.f, 0.f, 0.f);
        As[acol + 0][arow] = av.x;
        As[acol + 1][arow] = av.y;
        As[acol + 2][arow] = av.z;
        As[acol + 3][arow] = av.w;

        const float4 bv = *reinterpret_cast<const float4*>(
            W + (size_t)(k0 + brow) * N + bn0 + bcol);
        *reinterpret_cast<float4*>(&Bs[brow][bcol]) = bv;

        __syncthreads();
        #pragma unroll
        for (int k = 0; k < BK; k++) {
            float af[TM], bf[TN];
            #pragma unroll
            for (int i = 0; i < TM; i++) af[i] = As[k][ty * TM + i];
            #pragma unroll
            for (int j = 0; j < TN; j++) bf[j] = Bs[k][tx * TN + j];
            #pragma unroll
            for (int i = 0; i < TM; i++)
                #pragma unroll
                for (int j = 0; j < TN; j++)
                    acc[i][j] = fmaf(af[i], bf[j], acc[i][j]);
        }
        __syncthreads();
    }

    #pragma unroll
    for (int i = 0; i < TM; i++) {
        const int m = bm0 + ty * TM + i;
        if (m >= M) continue;
        size_t orow;
        if (REMAP) orow = (size_t)m + (size_t)(m / NTOK) * 1 + 1;
        else       orow = (size_t)m;
        #pragma unroll
        for (int j = 0; j < TN; j++) {
            const int nn = bn0 + tx * TN + j;
            float v = acc[i][j] + bias[nn];
            if (MODE == EP_BIAS_GELU)
                v = 0.5f * v * (1.f + erff(v * 0.70710678118654752f));
            if (MODE == EP_BIAS_RES)
                v += R[orow * N + nn];
            C[orow * N + nn] = v;
        }
    }
}

// ---------------------------------------------------------------------------
// graph-token fill
// ---------------------------------------------------------------------------
__global__ void fill_token_kernel(const float* __restrict__ gt, float* __restrict__ h)
{
    h[(size_t)blockIdx.x * NTOT * HID + threadIdx.x] = gt[threadIdx.x];
}

// ---------------------------------------------------------------------------
// Structural bias precompute
// ---------------------------------------------------------------------------
__global__ void bias_kernel(const int* __restrict__ len_spd,
                            const float* __restrict__ spd_emb,
                            const float* __restrict__ virt,
                            float* __restrict__ bias)
{
    const size_t idx = (size_t)blockIdx.x * blockDim.x + threadIdx.x;
    const size_t total = (size_t)BATCH * NHEAD * NTOT * NTOT;
    if (idx >= total) return;
    const int j = (int)(idx & 255);
    const int i = (int)((idx >> 8) & 255);
    const int h = (int)((idx >> 16) % NHEAD);
    const int b = (int)(idx / ((size_t)NHEAD * NTOT * NTOT));
    float v;
    if (i == 0 || j == 0) {
        v = virt[h];
    } else {
        const int lsp = len_spd[((size_t)b * NTOK + (i - 1)) * NTOK + (j - 1)];
        v = (lsp == 0) ? 0.f : spd_emb[lsp * NHEAD + h];
    }
    bias[idx] = v;
}

// ---------------------------------------------------------------------------
// LayerNorm (templated output dtype: fp32 or fp16)
// ---------------------------------------------------------------------------
template<bool OUTH>
__global__ __launch_bounds__(256) void ln_kernel(
    const float* __restrict__ X, const float* __restrict__ w,
    const float* __restrict__ b, void* __restrict__ Yout)
{
    const int row = blockIdx.x;
    const float* x = X + (size_t)row * HID;
    const int tid = threadIdx.x;

    float v0 = x[tid], v1 = x[tid + 256], v2 = x[tid + 512];
    float s = v0 + v1 + v2;

    __shared__ float red[8];
    #pragma unroll
    for (int o = 16; o > 0; o >>= 1) s += __shfl_xor_sync(~0u, s, o);
    if ((tid & 31) == 0) red[tid >> 5] = s;
    __syncthreads();
    float tot = red[0];
    #pragma unroll
    for (int wv = 1; wv < 8; wv++) tot += red[wv];
    const float mu = tot * (1.f / HID);
    __syncthreads();

    const float d0 = v0 - mu, d1 = v1 - mu, d2 = v2 - mu;
    float s2 = d0 * d0 + d1 * d1 + d2 * d2;
    #pragma unroll
    for (int o = 16; o > 0; o >>= 1) s2 += __shfl_xor_sync(~0u, s2, o);
    if ((tid & 31) == 0) red[tid >> 5] = s2;
    __syncthreads();
    float var = red[0];
    #pragma unroll
    for (int wv = 1; wv < 8; wv++) var += red[wv];
    var *= (1.f / HID);
    const float inv = rsqrtf(var + 1e-5f);

    const float y0 = d0 * inv * w[tid]       + b[tid];
    const float y1 = d1 * inv * w[tid + 256] + b[tid + 256];
    const float y2 = d2 * inv * w[tid + 512] + b[tid + 512];
    if (OUTH) {
        __half* Y = (__half*)Yout + (size_t)row * HID;
        Y[tid]       = __float2half_rn(y0);
        Y[tid + 256] = __float2half_rn(y1);
        Y[tid + 512] = __float2half_rn(y2);
    } else {
        float* Y = (float*)Yout + (size_t)row * HID;
        Y[tid] = y0; Y[tid + 256] = y1; Y[tid + 512] = y2;
    }
}

// ---------------------------------------------------------------------------
// Attention: one CTA per (b,h); fp32 math; fp16 output.
// ---------------------------------------------------------------------------
#define KVSTRIDE 65
#define ATTN_SMEM ((2 * 256 * KVSTRIDE + 64 + 256 + 256 + 16) * sizeof(float))

__global__ __launch_bounds__(256) void attn_kernel(
    const float* __restrict__ Q, const float* __restrict__ K,
    const float* __restrict__ V, const float* __restrict__ bias,
    __half* __restrict__ O)
{
    extern __shared__ float sm[];
    float* Ks   = sm;
    float* Vs   = Ks + 256 * KVSTRIDE;
    float* qs   = Vs + 256 * KVSTRIDE;
    float* pp   = qs + 64;
    float* part = pp + 256;
    float* redm = part + 256;
    float* reds = redm + 8;

    const int h = blockIdx.x;
    const int b = blockIdx.y;
    const int tid = threadIdx.x;
    const int lane = tid & 31;
    const int warp = tid >> 5;

    const size_t base = (size_t)b * NTOT * HID + (size_t)h * HDIM;

    for (int idx = tid; idx < 256 * 64; idx += 256) {
        const int j = idx >> 6, dd = idx & 63;
        Ks[j * KVSTRIDE + dd] = K[base + (size_t)j * HID + dd];
        Vs[j * KVSTRIDE + dd] = V[base + (size_t)j * HID + dd];
    }
    __syncthreads();

    const float* brow = bias + (((size_t)b * NHEAD + h) * NTOT) * NTOT;

    for (int i = 0; i < NTOT; i++) {
        if (tid < 64) qs[tid] = Q[base + (size_t)i * HID + tid];
        __syncthreads();

        float s = 0.f;
        const float* kr = &Ks[tid * KVSTRIDE];
        #pragma unroll 16
        for (int dd = 0; dd < 64; dd++) s = fmaf(qs[dd], kr[dd], s);
        s = s * 0.125f + brow[(size_t)i * NTOT + tid];

        float m = s;
        #pragma unroll
        for (int o = 16; o > 0; o >>= 1) m = fmaxf(m, __shfl_xor_sync(~0u, m, o));
        if (lane == 0) redm[warp] = m;
        __syncthreads();
        float mall = redm[0];
        #pragma unroll
        for (int wv = 1; wv < 8; wv++) mall = fmaxf(mall, redm[wv]);

        const float e = expf(s - mall);
        pp[tid] = e;
        float se = e;
        #pragma unroll
        for (int o = 16; o > 0; o >>= 1) se += __shfl_xor_sync(~0u, se, o);
        if (lane == 0) reds[warp] = se;
        __syncthreads();
        float sum = reds[0];
        #pragma unroll
        for (int wv = 1; wv < 8; wv++) sum += reds[wv];
        const float invsum = 1.f / sum;

        const int gg = tid >> 6, dd = tid & 63;
        float acc = 0.f;
        #pragma unroll 16
        for (int jj = 0; jj < 64; jj++) {
            const int jr = gg * 64 + jj;
            acc = fmaf(pp[jr], Vs[jr * KVSTRIDE + dd], acc);
        }
        part[tid] = acc;
        __syncthreads();

        if (tid < 64) {
            const float o4 = (part[tid] + part[64 + tid] + part[128 + tid] + part[192 + tid]) * invsum;
            O[base + (size_t)i * HID + tid] = __float2half_rn(o4);
        }
        __syncthreads();
    }
}

// ---------------------------------------------------------------------------
// Launch
// ---------------------------------------------------------------------------
extern "C" void kernel_launch(void* const* d_in, const int* in_sizes, int n_in,
                              void* d_out, int out_size)
{
    const float* x          = (const float*)d_in[0];
    const int*   len_spd    = (const int*)  d_in[1];
    const float* atom_W     = (const float*)d_in[2];
    const float* atom_b     = (const float*)d_in[3];
    const float* spd_emb    = (const float*)d_in[4];
    const float* graph_tok  = (const float*)d_in[5];
    const float* virt_dist  = (const float*)d_in[6];
    const float* ln1_w      = (const float*)d_in[7];
    const float* ln1_b      = (const float*)d_in[8];
    const float* Wq         = (const float*)d_in[9];
    const float* bq         = (const float*)d_in[10];
    const float* Wk         = (const float*)d_in[11];
    const float* bk         = (const float*)d_in[12];
    const float* Wv         = (const float*)d_in[13];
    const float* bv         = (const float*)d_in[14];
    const float* Wo         = (const float*)d_in[15];
    const float* bo         = (const float*)d_in[16];
    const float* ln2_w      = (const float*)d_in[17];
    const float* ln2_b      = (const float*)d_in[18];
    const float* W1         = (const float*)d_in[19];
    const float* b1         = (const float*)d_in[20];
    const float* W2         = (const float*)d_in[21];
    const float* b2         = (const float*)d_in[22];
    const float* fln_w      = (const float*)d_in[23];
    const float* fln_b      = (const float*)d_in[24];

    float *h, *q, *k, *v, *bias;
    __half *yh, *oh, *fh, *wt;
    cudaGetSymbolAddress((void**)&h,    g_h);
    cudaGetSymbolAddress((void**)&q,    g_q);
    cudaGetSymbolAddress((void**)&k,    g_k);
    cudaGetSymbolAddress((void**)&v,    g_v);
    cudaGetSymbolAddress((void**)&yh,   g_yh);
    cudaGetSymbolAddress((void**)&oh,   g_oh);
    cudaGetSymbolAddress((void**)&fh,   g_fh);
    cudaGetSymbolAddress((void**)&bias, g_bias);
    cudaGetSymbolAddress((void**)&wt,   g_wt);

    cudaFuncSetAttribute(attn_kernel, cudaFuncAttributeMaxDynamicSharedMemorySize,
                         (int)ATTN_SMEM);

    // 0) weight repack -> fragment-ordered fp16
    {
        const size_t szQ = (size_t)HID * HID, szF = (size_t)HID * FFN;
        dim3 gq((unsigned)(szQ / 2 / 256), 1, NLAYER);
        repack_h_kernel<<<gq, 256>>>(Wq, (__half2*)(wt + 0 * (size_t)WT_QKVO),
                                     HID, HID / 16, szQ, (size_t)WT_L / 2);
        repack_h_kernel<<<gq, 256>>>(Wk, (__half2*)(wt + 1 * (size_t)WT_QKVO),
                                     HID, HID / 16, szQ, (size_t)WT_L / 2);
        repack_h_kernel<<<gq, 256>>>(Wv, (__half2*)(wt + 2 * (size_t)WT_QKVO),
                                     HID, HID / 16, szQ, (size_t)WT_L / 2);
        repack_h_kernel<<<gq, 256>>>(Wo, (__half2*)(wt + 3 * (size_t)WT_QKVO),
                                     HID, HID / 16, szQ, (size_t)WT_L / 2);
        dim3 gf((unsigned)(szF / 2 / 256), 1, NLAYER);
        repack_h_kernel<<<gf, 256>>>(W1, (__half2*)(wt + 4 * (size_t)WT_QKVO),
                                     FFN, HID / 16, szF, (size_t)WT_L / 2);
        repack_h_kernel<<<gf, 256>>>(W2, (__half2*)(wt + 4 * (size_t)WT_QKVO + szF),
                                     HID, FFN / 16, szF, (size_t)WT_L / 2);
    }

    // 1) atom encoder (fp32, K=64, remapped rows)
    {
        dim3 grid(HID / BN, (MATOM + BM - 1) / BM);
        sgemm_kernel<EP_BIAS, true><<<grid, 256>>>(x, atom_W, atom_b, nullptr, h,
                                                   MATOM, DIN, HID);
    }
    // 2) graph token row 0 per batch
    fill_token_kernel<<<BATCH, HID>>>(graph_tok, h);

    // 3) structural bias (once)
    {
        const size_t total = (size_t)BATCH * NHEAD * NTOT * NTOT;
        bias_kernel<<<(unsigned)((total + 255) / 256), 256>>>(len_spd, spd_emb,
                                                              virt_dist, bias);
    }

    const dim3 gHID(HID / 128, MROWS / 128);   // 6 x 64
    const dim3 gFFN(FFN / 128, MROWS / 128);   // 24 x 64

    for (int l = 0; l < NLAYER; l++) {
        const size_t bofs  = (size_t)l * HID;
        const size_t b1ofs = (size_t)l * FFN;
        __half* wl = wt + (size_t)l * WT_L;
        const size_t szF = (size_t)HID * FFN;

        ln_kernel<true><<<MROWS, 256>>>(h, ln1_w + bofs, ln1_b + bofs, yh);

        hgemm_kernel<EP_BIAS, false><<<gHID, 256>>>(
            yh, wl + 0 * (size_t)WT_QKVO, bq + bofs, nullptr, q, HID, HID);
        hgemm_kernel<EP_BIAS, false><<<gHID, 256>>>(
            yh, wl + 1 * (size_t)WT_QKVO, bk + bofs, nullptr, k, HID, HID);
        hgemm_kernel<EP_BIAS, false><<<gHID, 256>>>(
            yh, wl + 2 * (size_t)WT_QKVO, bv + bofs, nullptr, v, HID, HID);

        attn_kernel<<<dim3(NHEAD, BATCH), 256, ATTN_SMEM>>>(q, k, v, bias, oh);

        hgemm_kernel<EP_BIAS_RES, false><<<gHID, 256>>>(
            oh, wl + 3 * (size_t)WT_QKVO, bo + bofs, h, h, HID, HID);

        ln_kernel<true><<<MROWS, 256>>>(h, ln2_w + bofs, ln2_b + bofs, yh);

        hgemm_kernel<EP_BIAS_GELU, true><<<gFFN, 256>>>(
            yh, wl + 4 * (size_t)WT_QKVO, b1 + b1ofs, nullptr, fh, HID, FFN);
        hgemm_kernel<EP_BIAS_RES, false><<<gHID, 256>>>(
            fh, wl + 4 * (size_t)WT_QKVO + szF, b2 + bofs, h, h, FFN, HID);
    }

    ln_kernel<false><<<MROWS, 256>>>(h, fln_w, fln_b, d_out);
}

// round 9
// speedup vs baseline: 1.2919x; 1.0286x over previous
#include <cuda_runtime.h>
#include <cuda_fp16.h>
#include <math.h>
#include <stdint.h>

// ---------------------------------------------------------------------------
// Problem constants
// ---------------------------------------------------------------------------
#define BATCH   32
#define NTOK    255
#define NTOT    256
#define DIN     64
#define NHEAD   12
#define HID     768
#define FFN     3072
#define NLAYER  6
#define HDIM    64
#define MROWS   (BATCH*NTOT) // 8192
#define MATOM   (BATCH*NTOK) // 8160

// ---------------------------------------------------------------------------
// Scratch (device globals; no allocations allowed)
// ---------------------------------------------------------------------------
__device__ __align__(256) float  g_h  [(size_t)MROWS*HID];
__device__ __align__(256) float  g_q  [(size_t)MROWS*HID];
__device__ __align__(256) float  g_k  [(size_t)MROWS*HID];
__device__ __align__(256) float  g_v  [(size_t)MROWS*HID];
__device__ __align__(256) __half g_yh [(size_t)MROWS*HID];
__device__ __align__(256) __half g_oh [(size_t)MROWS*HID];
__device__ __align__(256) __half g_fh [(size_t)MROWS*FFN];
__device__ __align__(256) float  g_bias[(size_t)BATCH*NHEAD*NTOT*NTOT];

// fragment-packed fp16 weights (per layer: Wq,Wk,Wv,Wo,W1,W2 contiguous)
#define WT_QKVO (HID*HID)                  // halves
#define WT_L    (4*WT_QKVO + 2*HID*FFN)    // halves per layer
__device__ __align__(256) __half g_wt[(size_t)NLAYER*WT_L];

enum { EP_BIAS = 0, EP_BIAS_RES = 1, EP_BIAS_GELU = 2 };

// ---------------------------------------------------------------------------
// helpers
// ---------------------------------------------------------------------------
__device__ __forceinline__ void cp16(void* smem, const void* gmem) {
    unsigned s = (unsigned)__cvta_generic_to_shared(smem);
    asm volatile("cp.async.cg.shared.global [%0], [%1], 16;" :: "r"(s), "l"(gmem));
}
__device__ __forceinline__ void mmah(float c[4], const unsigned a[4],
                                     unsigned b0, unsigned b1) {
    asm volatile(
        "mma.sync.aligned.m16n8k16.row.col.f32.f16.f16.f32 "
        "{%0,%1,%2,%3}, {%4,%5,%6,%7}, {%8,%9}, {%0,%1,%2,%3};"
        : "+f"(c[0]), "+f"(c[1]), "+f"(c[2]), "+f"(c[3])
        : "r"(a[0]), "r"(a[1]), "r"(a[2]), "r"(a[3]), "r"(b0), "r"(b1));
}

// ---------------------------------------------------------------------------
// Weight repack: W[K][N] fp32 -> fragment-ordered fp16 half2 (per matrix)
//   half2 idx = ((nt*ktiles + kt)*8 + p)*128 + lane*4 + c
//   k = kt*16 + (c&1)*8 + 2q ; n = nt*128 + (p*2 + (c>>1))*8 + g
// ---------------------------------------------------------------------------
__device__ __forceinline__ void repack_one(
    const float* __restrict__ in, __half2* __restrict__ out,
    unsigned idx, int N, int ktiles)
{
    const int c    = idx & 3;
    const int lane = (idx >> 2) & 31;
    const int p    = (idx >> 7) & 7;
    const unsigned rest = idx >> 10;
    const int kt = (int)(rest % (unsigned)ktiles);
    const int nt = (int)(rest / (unsigned)ktiles);
    const int g = lane >> 2, q = lane & 3;
    const int k = kt * 16 + (c & 1) * 8 + q * 2;
    const int n = nt * 128 + (p * 2 + (c >> 1)) * 8 + g;
    out[idx] = __floats2half2_rn(in[(size_t)k * N + n], in[(size_t)(k + 1) * N + n]);
}

// QKVO repack: grid.z = 4*NLAYER ; z&3 = type, z>>2 = layer
__global__ __launch_bounds__(256) void repack_qkvo_kernel(
    const float* __restrict__ Wq, const float* __restrict__ Wk,
    const float* __restrict__ Wv, const float* __restrict__ Wo,
    __half2* __restrict__ wt)
{
    const int z = blockIdx.z, type = z & 3, layer = z >> 2;
    const float* ins[4] = { Wq, Wk, Wv, Wo };
    const float* in = ins[type] + (size_t)layer * HID * HID;
    __half2* out = wt + ((size_t)layer * WT_L + (size_t)type * WT_QKVO) / 2;
    repack_one(in, out, blockIdx.x * 256u + threadIdx.x, HID, HID / 16);
}

// W1/W2 repack: grid.z = 2*NLAYER ; z<NLAYER -> W1 layer z ; else W2
__global__ __launch_bounds__(256) void repack_w12_kernel(
    const float* __restrict__ W1, const float* __restrict__ W2,
    __half2* __restrict__ wt)
{
    const int z = blockIdx.z;
    const size_t szF = (size_t)HID * FFN;
    const unsigned idx = blockIdx.x * 256u + threadIdx.x;
    if (z < NLAYER) {
        const float* in = W1 + (size_t)z * szF;
        __half2* out = wt + ((size_t)z * WT_L + 4 * (size_t)WT_QKVO) / 2;
        repack_one(in, out, idx, FFN, HID / 16);
    } else {
        const int layer = z - NLAYER;
        const float* in = W2 + (size_t)layer * szF;
        __half2* out = wt + ((size_t)layer * WT_L + 4 * (size_t)WT_QKVO + szF) / 2;
        repack_one(in, out, idx, HID, FFN / 16);
    }
}

// ---------------------------------------------------------------------------
// fp16 mma.sync GEMM, 4-stage cp.async pipeline, 1 sync/iter.
// CTA 128x128, 256 thr (8 warps, 4xM 2xN, warp tile 32x64), K-chunk 16.
// QKV mode: grid.x spans Wq|Wk|Wv packed n-tiles; per-CTA output select.
// ---------------------------------------------------------------------------
template<int MODE, bool OUTH, bool QKV>
__global__ __launch_bounds__(256, 2) void hgemm_kernel(
    const __half* __restrict__ A, const __half* __restrict__ Wpk,
    const float* __restrict__ bias0, const float* __restrict__ bias1,
    const float* __restrict__ bias2, const float* __restrict__ R,
    void* __restrict__ C0, void* __restrict__ C1, void* __restrict__ C2,
    int K, int N)
{
    __shared__ __half stA[4][128 * 24];   // 4 x 6144 B
    __shared__ uint4  fgB[4][256];        // 4 x 4096 B

    const int tid  = threadIdx.x;
    const int lane = tid & 31;
    const int warp = tid >> 5;
    const int g    = lane >> 2;
    const int q    = lane & 3;
    const int bm0  = blockIdx.y * 128;
    const int wn   = (warp & 1) * 64;
    const int wm   = (warp >> 1) * 32;

    int bn0 = blockIdx.x * 128;
    const float* bias = bias0;
    void* Cout = C0;
    if (QKV) {
        const int type = blockIdx.x / 6;         // 0=q 1=k 2=v
        bn0 -= type * 768;
        bias = (type == 0) ? bias0 : (type == 1 ? bias1 : bias2);
        Cout = (type == 0) ? C0 : (type == 1 ? C1 : C2);
    }

    const int nc = K / 16;
    const __half* Ag = A + (size_t)(bm0 + (tid >> 1)) * K + (tid & 1) * 8;
    const uint4*  Bg = reinterpret_cast<const uint4*>(Wpk)
                       + (size_t)blockIdx.x * nc * 256 + tid;
    const int saOfs = (tid >> 1) * 24 + (tid & 1) * 8;

    float acc[2][8][4];
    #pragma unroll
    for (int t = 0; t < 2; t++)
        #pragma unroll
        for (int j = 0; j < 8; j++)
            #pragma unroll
            for (int r = 0; r < 4; r++) acc[t][j][r] = 0.f;

    auto issue = [&](int s, int kt) {
        cp16(&stA[s][saOfs], Ag + kt * 16);
        cp16(&fgB[s][tid], Bg + (size_t)kt * 256);
        asm volatile("cp.async.commit_group;");
    };

    issue(0, 0); issue(1, 1); issue(2, 2);

    for (int c = 0; c < nc; c++) {
        if (c <= nc - 3)      asm volatile("cp.async.wait_group 2;");
        else if (c == nc - 2) asm volatile("cp.async.wait_group 1;");
        else                  asm volatile("cp.async.wait_group 0;");
        __syncthreads();
        if (c + 3 < nc) issue((c + 3) & 3, c + 3);

        const int buf = c & 3;
        unsigned a[2][4];
        #pragma unroll
        for (int t = 0; t < 2; t++) {
            const __half* st = &stA[buf][(wm + t * 16 + g) * 24 + 2 * q];
            a[t][0] = *reinterpret_cast<const unsigned*>(st);
            a[t][1] = *reinterpret_cast<const unsigned*>(st + 8 * 24);
            a[t][2] = *reinterpret_cast<const unsigned*>(st + 8);
            a[t][3] = *reinterpret_cast<const unsigned*>(st + 8 * 24 + 8);
        }
        #pragma unroll
        for (int jp = 0; jp < 4; jp++) {
            const uint4 v = fgB[buf][((warp & 1) * 4 + jp) * 32 + lane];
            mmah(acc[0][jp * 2    ], a[0], v.x, v.y);
            mmah(acc[0][jp * 2 + 1], a[0], v.z, v.w);
            mmah(acc[1][jp * 2    ], a[1], v.x, v.y);
            mmah(acc[1][jp * 2 + 1], a[1], v.z, v.w);
        }
    }

    // epilogue
    #pragma unroll
    for (int t = 0; t < 2; t++) {
        const int m0 = bm0 + wm + t * 16 + g;
        const int m1 = m0 + 8;
        #pragma unroll
        for (int j = 0; j < 8; j++) {
            const int n0 = bn0 + wn + j * 8 + q * 2;
            const float b0 = bias[n0], b1 = bias[n0 + 1];
            float v00 = acc[t][j][0] + b0;
            float v01 = acc[t][j][1] + b1;
            float v10 = acc[t][j][2] + b0;
            float v11 = acc[t][j][3] + b1;
            if (MODE == EP_BIAS_GELU) {
                v00 = 0.5f * v00 * (1.f + erff(v00 * 0.70710678118654752f));
                v01 = 0.5f * v01 * (1.f + erff(v01 * 0.70710678118654752f));
                v10 = 0.5f * v10 * (1.f + erff(v10 * 0.70710678118654752f));
                v11 = 0.5f * v11 * (1.f + erff(v11 * 0.70710678118654752f));
            }
            if (MODE == EP_BIAS_RES) {
                const float2 r0 = *reinterpret_cast<const float2*>(R + (size_t)m0 * N + n0);
                const float2 r1 = *reinterpret_cast<const float2*>(R + (size_t)m1 * N + n0);
                v00 += r0.x; v01 += r0.y; v10 += r1.x; v11 += r1.y;
            }
            if (OUTH) {
                __half2* C = (__half2*)Cout;
                C[((size_t)m0 * N + n0) >> 1] = __floats2half2_rn(v00, v01);
                C[((size_t)m1 * N + n0) >> 1] = __floats2half2_rn(v10, v11);
            } else {
                float* C = (float*)Cout;
                *reinterpret_cast<float2*>(C + (size_t)m0 * N + n0) = make_float2(v00, v01);
                *reinterpret_cast<float2*>(C + (size_t)m1 * N + n0) = make_float2(v10, v11);
            }
        }
    }
}

// ---------------------------------------------------------------------------
// fp32 SGEMM (atom-encoder only: K=64, row remap)
// ---------------------------------------------------------------------------
#define BM 128
#define BN 128
#define BK 8
#define TM 8
#define TN 8

__global__ __launch_bounds__(256) void sgemm_atom_kernel(
    const float* __restrict__ A, const float* __restrict__ W,
    const float* __restrict__ bias, float* __restrict__ C,
    int M, int K, int N)
{
    __shared__ float As[BK][BM];
    __shared__ float Bs[BK][BN];

    const int tid = threadIdx.x;
    const int bm0 = blockIdx.y * BM;
    const int bn0 = blockIdx.x * BN;
    const int tx = tid & 15;
    const int ty = tid >> 4;

    float acc[TM][TN];
    #pragma unroll
    for (int i = 0; i < TM; i++)
        #pragma unroll
        for (int j = 0; j < TN; j++) acc[i][j] = 0.f;

    const int arow = tid >> 1;
    const int acol = (tid & 1) * 4;
    const int brow = tid >> 5;
    const int bcol = (tid & 31) * 4;

    for (int k0 = 0; k0 < K; k0 += BK) {
        float4 av;
        const int gm = bm0 + arow;
        if (gm < M)
            av = *reinterpret_cast<const float4*>(A + (size_t)gm * K + k0 + acol);
        else
            av = make_float4(0.f, 0.f, 0.f, 0.f);
        As[acol + 0][arow] = av.x;
        As[acol + 1][arow] = av.y;
        As[acol + 2][arow] = av.z;
        As[acol + 3][arow] = av.w;

        const float4 bv = *reinterpret_cast<const float4*>(
            W + (size_t)(k0 + brow) * N + bn0 + bcol);
        *reinterpret_cast<float4*>(&Bs[brow][bcol]) = bv;

        __syncthreads();
        #pragma unroll
        for (int k = 0; k < BK; k++) {
            float af[TM], bf[TN];
            #pragma unroll
            for (int i = 0; i < TM; i++) af[i] = As[k][ty * TM + i];
            #pragma unroll
            for (int j = 0; j < TN; j++) bf[j] = Bs[k][tx * TN + j];
            #pragma unroll
            for (int i = 0; i < TM; i++)
                #pragma unroll
                for (int j = 0; j < TN; j++)
                    acc[i][j] = fmaf(af[i], bf[j], acc[i][j]);
        }
        __syncthreads();
    }

    #pragma unroll
    for (int i = 0; i < TM; i++) {
        const int m = bm0 + ty * TM + i;
        if (m >= M) continue;
        const size_t orow = (size_t)m + (size_t)(m / NTOK) + 1;
        #pragma unroll
        for (int j = 0; j < TN; j++) {
            const int nn = bn0 + tx * TN + j;
            C[orow * N + nn] = acc[i][j] + bias[nn];
        }
    }
}

// ---------------------------------------------------------------------------
// fused graph-token fill + structural bias
// ---------------------------------------------------------------------------
#define NBIASBLK ((unsigned)((size_t)BATCH*NHEAD*NTOT*NTOT/256))

__global__ void fillbias_kernel(const int* __restrict__ len_spd,
                                const float* __restrict__ spd_emb,
                                const float* __restrict__ virt,
                                const float* __restrict__ gt,
                                float* __restrict__ bias,
                                float* __restrict__ h)
{
    if (blockIdx.x < NBIASBLK) {
        const size_t idx = (size_t)blockIdx.x * 256 + threadIdx.x;
        const int j = (int)(idx & 255);
        const int i = (int)((idx >> 8) & 255);
        const int hh = (int)((idx >> 16) % NHEAD);
        const int b = (int)(idx / ((size_t)NHEAD * NTOT * NTOT));
        float v;
        if (i == 0 || j == 0) {
            v = virt[hh];
        } else {
            const int lsp = len_spd[((size_t)b * NTOK + (i - 1)) * NTOK + (j - 1)];
            v = (lsp == 0) ? 0.f : spd_emb[lsp * NHEAD + hh];
        }
        bias[idx] = v;
    } else {
        const unsigned r = (blockIdx.x - NBIASBLK) * 256 + threadIdx.x;
        const int b = r / HID, t = r % HID;
        h[(size_t)b * NTOT * HID + t] = gt[t];
    }
}

// ---------------------------------------------------------------------------
// LayerNorm (templated output dtype)
// ---------------------------------------------------------------------------
template<bool OUTH>
__global__ __launch_bounds__(256) void ln_kernel(
    const float* __restrict__ X, const float* __restrict__ w,
    const float* __restrict__ b, void* __restrict__ Yout)
{
    const int row = blockIdx.x;
    const float* x = X + (size_t)row * HID;
    const int tid = threadIdx.x;

    float v0 = x[tid], v1 = x[tid + 256], v2 = x[tid + 512];
    float s = v0 + v1 + v2;

    __shared__ float red[8];
    #pragma unroll
    for (int o = 16; o > 0; o >>= 1) s += __shfl_xor_sync(~0u, s, o);
    if ((tid & 31) == 0) red[tid >> 5] = s;
    __syncthreads();
    float tot = red[0];
    #pragma unroll
    for (int wv = 1; wv < 8; wv++) tot += red[wv];
    const float mu = tot * (1.f / HID);
    __syncthreads();

    const float d0 = v0 - mu, d1 = v1 - mu, d2 = v2 - mu;
    float s2 = d0 * d0 + d1 * d1 + d2 * d2;
    #pragma unroll
    for (int o = 16; o > 0; o >>= 1) s2 += __shfl_xor_sync(~0u, s2, o);
    if ((tid & 31) == 0) red[tid >> 5] = s2;
    __syncthreads();
    float var = red[0];
    #pragma unroll
    for (int wv = 1; wv < 8; wv++) var += red[wv];
    var *= (1.f / HID);
    const float inv = rsqrtf(var + 1e-5f);

    const float y0 = d0 * inv * w[tid]       + b[tid];
    const float y1 = d1 * inv * w[tid + 256] + b[tid + 256];
    const float y2 = d2 * inv * w[tid + 512] + b[tid + 512];
    if (OUTH) {
        __half* Y = (__half*)Yout + (size_t)row * HID;
        Y[tid]       = __float2half_rn(y0);
        Y[tid + 256] = __float2half_rn(y1);
        Y[tid + 512] = __float2half_rn(y2);
    } else {
        float* Y = (float*)Yout + (size_t)row * HID;
        Y[tid] = y0; Y[tid + 256] = y1; Y[tid + 512] = y2;
    }
}

// ---------------------------------------------------------------------------
// Attention: one CTA per (b,h); fp32 math; fp16 output.
// ---------------------------------------------------------------------------
#define KVSTRIDE 65
#define ATTN_SMEM ((2 * 256 * KVSTRIDE + 64 + 256 + 256 + 16) * sizeof(float))

__global__ __launch_bounds__(256) void attn_kernel(
    const float* __restrict__ Q, const float* __restrict__ K,
    const float* __restrict__ V, const float* __restrict__ bias,
    __half* __restrict__ O)
{
    extern __shared__ float sm[];
    float* Ks   = sm;
    float* Vs   = Ks + 256 * KVSTRIDE;
    float* qs   = Vs + 256 * KVSTRIDE;
    float* pp   = qs + 64;
    float* part = pp + 256;
    float* redm = part + 256;
    float* reds = redm + 8;

    const int h = blockIdx.x;
    const int b = blockIdx.y;
    const int tid = threadIdx.x;
    const int lane = tid & 31;
    const int warp = tid >> 5;

    const size_t base = (size_t)b * NTOT * HID + (size_t)h * HDIM;

    for (int idx = tid; idx < 256 * 64; idx += 256) {
        const int j = idx >> 6, dd = idx & 63;
        Ks[j * KVSTRIDE + dd] = K[base + (size_t)j * HID + dd];
        Vs[j * KVSTRIDE + dd] = V[base + (size_t)j * HID + dd];
    }
    __syncthreads();

    const float* brow = bias + (((size_t)b * NHEAD + h) * NTOT) * NTOT;

    for (int i = 0; i < NTOT; i++) {
        if (tid < 64) qs[tid] = Q[base + (size_t)i * HID + tid];
        __syncthreads();

        float s = 0.f;
        const float* kr = &Ks[tid * KVSTRIDE];
        #pragma unroll 16
        for (int dd = 0; dd < 64; dd++) s = fmaf(qs[dd], kr[dd], s);
        s = s * 0.125f + brow[(size_t)i * NTOT + tid];

        float m = s;
        #pragma unroll
        for (int o = 16; o > 0; o >>= 1) m = fmaxf(m, __shfl_xor_sync(~0u, m, o));
        if (lane == 0) redm[warp] = m;
        __syncthreads();
        float mall = redm[0];
        #pragma unroll
        for (int wv = 1; wv < 8; wv++) mall = fmaxf(mall, redm[wv]);

        const float e = expf(s - mall);
        pp[tid] = e;
        float se = e;
        #pragma unroll
        for (int o = 16; o > 0; o >>= 1) se += __shfl_xor_sync(~0u, se, o);
        if (lane == 0) reds[warp] = se;
        __syncthreads();
        float sum = reds[0];
        #pragma unroll
        for (int wv = 1; wv < 8; wv++) sum += reds[wv];
        const float invsum = 1.f / sum;

        const int gg = tid >> 6, dd = tid & 63;
        float acc = 0.f;
        #pragma unroll 16
        for (int jj = 0; jj < 64; jj++) {
            const int jr = gg * 64 + jj;
            acc = fmaf(pp[jr], Vs[jr * KVSTRIDE + dd], acc);
        }
        part[tid] = acc;
        __syncthreads();

        if (tid < 64) {
            const float o4 = (part[tid] + part[64 + tid] + part[128 + tid] + part[192 + tid]) * invsum;
            O[base + (size_t)i * HID + tid] = __float2half_rn(o4);
        }
        __syncthreads();
    }
}

// ---------------------------------------------------------------------------
// Launch
// ---------------------------------------------------------------------------
extern "C" void kernel_launch(void* const* d_in, const int* in_sizes, int n_in,
                              void* d_out, int out_size)
{
    const float* x          = (const float*)d_in[0];
    const int*   len_spd    = (const int*)  d_in[1];
    const float* atom_W     = (const float*)d_in[2];
    const float* atom_b     = (const float*)d_in[3];
    const float* spd_emb    = (const float*)d_in[4];
    const float* graph_tok  = (const float*)d_in[5];
    const float* virt_dist  = (const float*)d_in[6];
    const float* ln1_w      = (const float*)d_in[7];
    const float* ln1_b      = (const float*)d_in[8];
    const float* Wq         = (const float*)d_in[9];
    const float* bq         = (const float*)d_in[10];
    const float* Wk         = (const float*)d_in[11];
    const float* bk         = (const float*)d_in[12];
    const float* Wv         = (const float*)d_in[13];
    const float* bv         = (const float*)d_in[14];
    const float* Wo         = (const float*)d_in[15];
    const float* bo         = (const float*)d_in[16];
    const float* ln2_w      = (const float*)d_in[17];
    const float* ln2_b      = (const float*)d_in[18];
    const float* W1         = (const float*)d_in[19];
    const float* b1         = (const float*)d_in[20];
    const float* W2         = (const float*)d_in[21];
    const float* b2         = (const float*)d_in[22];
    const float* fln_w      = (const float*)d_in[23];
    const float* fln_b      = (const float*)d_in[24];

    float *h, *q, *k, *v, *bias;
    __half *yh, *oh, *fh, *wt;
    cudaGetSymbolAddress((void**)&h,    g_h);
    cudaGetSymbolAddress((void**)&q,    g_q);
    cudaGetSymbolAddress((void**)&k,    g_k);
    cudaGetSymbolAddress((void**)&v,    g_v);
    cudaGetSymbolAddress((void**)&yh,   g_yh);
    cudaGetSymbolAddress((void**)&oh,   g_oh);
    cudaGetSymbolAddress((void**)&fh,   g_fh);
    cudaGetSymbolAddress((void**)&bias, g_bias);
    cudaGetSymbolAddress((void**)&wt,   g_wt);

    cudaFuncSetAttribute(attn_kernel, cudaFuncAttributeMaxDynamicSharedMemorySize,
                         (int)ATTN_SMEM);

    const size_t szQ = (size_t)HID * HID, szF = (size_t)HID * FFN;

    // L1: atom encoder (fp32, remapped rows)
    {
        dim3 grid(HID / BN, (MATOM + BM - 1) / BM);
        sgemm_atom_kernel<<<grid, 256>>>(x, atom_W, atom_b, h, MATOM, DIN, HID);
    }
    // L2: graph-token fill + structural bias (fused)
    fillbias_kernel<<<NBIASBLK + (BATCH * HID / 256), 256>>>(
        len_spd, spd_emb, virt_dist, graph_tok, bias, h);
    // L3: repack QKVO (all layers)
    repack_qkvo_kernel<<<dim3((unsigned)(szQ / 2 / 256), 1, 4 * NLAYER), 256>>>(
        Wq, Wk, Wv, Wo, (__half2*)wt);
    // L4: repack W1+W2 (all layers)
    repack_w12_kernel<<<dim3((unsigned)(szF / 2 / 256), 1, 2 * NLAYER), 256>>>(
        W1, W2, (__half2*)wt);
    // L5: ln1 layer 0
    ln_kernel<true><<<MROWS, 256>>>(h, ln1_w, ln1_b, yh);
    // L6: QKV fused hgemm layer 0  <-- ncu capture target (-s 5 -c 1)

    const dim3 gQKV(18, MROWS / 128);
    const dim3 gHID(HID / 128, MROWS / 128);
    const dim3 gFFN(FFN / 128, MROWS / 128);

    for (int l = 0; l < NLAYER; l++) {
        const size_t bofs  = (size_t)l * HID;
        const size_t b1ofs = (size_t)l * FFN;
        __half* wl = wt + (size_t)l * WT_L;

        if (l > 0)
            ln_kernel<true><<<MROWS, 256>>>(h, ln1_w + bofs, ln1_b + bofs, yh);

        hgemm_kernel<EP_BIAS, false, true><<<gQKV, 256>>>(
            yh, wl, bq + bofs, bk + bofs, bv + bofs, nullptr,
            q, k, v, HID, HID);

        attn_kernel<<<dim3(NHEAD, BATCH), 256, ATTN_SMEM>>>(q, k, v, bias, oh);

        hgemm_kernel<EP_BIAS_RES, false, false><<<gHID, 256>>>(
            oh, wl + 3 * (size_t)WT_QKVO, bo + bofs, nullptr, nullptr, h,
            h, nullptr, nullptr, HID, HID);

        ln_kernel<true><<<MROWS, 256>>>(h, ln2_w + bofs, ln2_b + bofs, yh);

        hgemm_kernel<EP_BIAS_GELU, true, false><<<gFFN, 256>>>(
            yh, wl + 4 * (size_t)WT_QKVO, b1 + b1ofs, nullptr, nullptr, nullptr,
            fh, nullptr, nullptr, HID, FFN);
        hgemm_kernel<EP_BIAS_RES, false, false><<<gHID, 256>>>(
            fh, wl + 4 * (size_t)WT_QKVO + szF, b2 + bofs, nullptr, nullptr, h,
            h, nullptr, nullptr, FFN, HID);
    }

    ln_kernel<false><<<MROWS, 256>>>(h, fln_w, fln_b, d_out);
}

// round 10
// speedup vs baseline: 3.0671x; 2.3741x over previous
#include <cuda_runtime.h>
#include <cuda_fp16.h>
#include <math.h>
#include <stdint.h>

// ---------------------------------------------------------------------------
// Problem constants
// ---------------------------------------------------------------------------
#define BATCH   32
#define NTOK    255
#define NTOT    256
#define DIN     64
#define NHEAD   12
#define HID     768
#define FFN     3072
#define NLAYER  6
#define HDIM    64
#define MROWS   (BATCH*NTOT) // 8192
#define MATOM   (BATCH*NTOK) // 8160

// ---------------------------------------------------------------------------
// Scratch (device globals; no allocations allowed)
// ---------------------------------------------------------------------------
__device__ __align__(256) float  g_h  [(size_t)MROWS*HID];
__device__ __align__(256) __half g_yh [(size_t)MROWS*HID];
__device__ __align__(256) __half g_qh [(size_t)MROWS*HID];
__device__ __align__(256) __half g_kh [(size_t)MROWS*HID];
__device__ __align__(256) __half g_vh [(size_t)MROWS*HID];
__device__ __align__(256) __half g_oh [(size_t)MROWS*HID];
__device__ __align__(256) __half g_fh [(size_t)MROWS*FFN];
__device__ __align__(256) float  g_bias[(size_t)BATCH*NHEAD*NTOT*NTOT];

// fragment-packed fp16 weights (per layer: Wq,Wk,Wv,Wo,W1,W2 contiguous)
#define WT_QKVO (HID*HID)                  // halves
#define WT_L    (4*WT_QKVO + 2*HID*FFN)    // halves per layer
__device__ __align__(256) __half g_wt[(size_t)NLAYER*WT_L];

enum { EP_BIAS = 0, EP_BIAS_RES = 1, EP_BIAS_GELU = 2 };

// ---------------------------------------------------------------------------
// helpers
// ---------------------------------------------------------------------------
__device__ __forceinline__ void cp16(void* smem, const void* gmem) {
    unsigned s = (unsigned)__cvta_generic_to_shared(smem);
    asm volatile("cp.async.cg.shared.global [%0], [%1], 16;" :: "r"(s), "l"(gmem));
}
__device__ __forceinline__ void mmah(float c[4], const unsigned a[4],
                                     unsigned b0, unsigned b1) {
    asm volatile(
        "mma.sync.aligned.m16n8k16.row.col.f32.f16.f16.f32 "
        "{%0,%1,%2,%3}, {%4,%5,%6,%7}, {%8,%9}, {%0,%1,%2,%3};"
        : "+f"(c[0]), "+f"(c[1]), "+f"(c[2]), "+f"(c[3])
        : "r"(a[0]), "r"(a[1]), "r"(a[2]), "r"(a[3]), "r"(b0), "r"(b1));
}

// ---------------------------------------------------------------------------
// Weight repack: W[K][N] fp32 -> fragment-ordered fp16 half2 (per matrix)
// ---------------------------------------------------------------------------
__device__ __forceinline__ void repack_one(
    const float* __restrict__ in, __half2* __restrict__ out,
    unsigned idx, int N, int ktiles)
{
    const int c    = idx & 3;
    const int lane = (idx >> 2) & 31;
    const int p    = (idx >> 7) & 7;
    const unsigned rest = idx >> 10;
    const int kt = (int)(rest % (unsigned)ktiles);
    const int nt = (int)(rest / (unsigned)ktiles);
    const int g = lane >> 2, q = lane & 3;
    const int k = kt * 16 + (c & 1) * 8 + q * 2;
    const int n = nt * 128 + (p * 2 + (c >> 1)) * 8 + g;
    out[idx] = __floats2half2_rn(in[(size_t)k * N + n], in[(size_t)(k + 1) * N + n]);
}

__global__ __launch_bounds__(256) void repack_qkvo_kernel(
    const float* __restrict__ Wq, const float* __restrict__ Wk,
    const float* __restrict__ Wv, const float* __restrict__ Wo,
    __half2* __restrict__ wt)
{
    const int z = blockIdx.z, type = z & 3, layer = z >> 2;
    const float* ins[4] = { Wq, Wk, Wv, Wo };
    const float* in = ins[type] + (size_t)layer * HID * HID;
    __half2* out = wt + ((size_t)layer * WT_L + (size_t)type * WT_QKVO) / 2;
    repack_one(in, out, blockIdx.x * 256u + threadIdx.x, HID, HID / 16);
}

__global__ __launch_bounds__(256) void repack_w12_kernel(
    const float* __restrict__ W1, const float* __restrict__ W2,
    __half2* __restrict__ wt)
{
    const int z = blockIdx.z;
    const size_t szF = (size_t)HID * FFN;
    const unsigned idx = blockIdx.x * 256u + threadIdx.x;
    if (z < NLAYER) {
        const float* in = W1 + (size_t)z * szF;
        __half2* out = wt + ((size_t)z * WT_L + 4 * (size_t)WT_QKVO) / 2;
        repack_one(in, out, idx, FFN, HID / 16);
    } else {
        const int layer = z - NLAYER;
        const float* in = W2 + (size_t)layer * szF;
        __half2* out = wt + ((size_t)layer * WT_L + 4 * (size_t)WT_QKVO + szF) / 2;
        repack_one(in, out, idx, HID, FFN / 16);
    }
}

// ---------------------------------------------------------------------------
// fp16 mma.sync GEMM, 4-stage cp.async pipeline, 1 sync/iter.
// CTA 128x128, 256 thr (8 warps, 4xM 2xN, warp tile 32x64), K-chunk 16.
// ---------------------------------------------------------------------------
template<int MODE, bool OUTH, bool QKV>
__global__ __launch_bounds__(256, 2) void hgemm_kernel(
    const __half* __restrict__ A, const __half* __restrict__ Wpk,
    const float* __restrict__ bias0, const float* __restrict__ bias1,
    const float* __restrict__ bias2, const float* __restrict__ R,
    void* __restrict__ C0, void* __restrict__ C1, void* __restrict__ C2,
    int K, int N)
{
    __shared__ __half stA[4][128 * 24];
    __shared__ uint4  fgB[4][256];

    const int tid  = threadIdx.x;
    const int lane = tid & 31;
    const int warp = tid >> 5;
    const int g    = lane >> 2;
    const int q    = lane & 3;
    const int bm0  = blockIdx.y * 128;
    const int wn   = (warp & 1) * 64;
    const int wm   = (warp >> 1) * 32;

    int bn0 = blockIdx.x * 128;
    const float* bias = bias0;
    void* Cout = C0;
    if (QKV) {
        const int type = blockIdx.x / 6;         // 0=q 1=k 2=v
        bn0 -= type * 768;
        bias = (type == 0) ? bias0 : (type == 1 ? bias1 : bias2);
        Cout = (type == 0) ? C0 : (type == 1 ? C1 : C2);
    }

    const int nc = K / 16;
    const __half* Ag = A + (size_t)(bm0 + (tid >> 1)) * K + (tid & 1) * 8;
    const uint4*  Bg = reinterpret_cast<const uint4*>(Wpk)
                       + (size_t)blockIdx.x * nc * 256 + tid;
    const int saOfs = (tid >> 1) * 24 + (tid & 1) * 8;

    float acc[2][8][4];
    #pragma unroll
    for (int t = 0; t < 2; t++)
        #pragma unroll
        for (int j = 0; j < 8; j++)
            #pragma unroll
            for (int r = 0; r < 4; r++) acc[t][j][r] = 0.f;

    auto issue = [&](int s, int kt) {
        cp16(&stA[s][saOfs], Ag + kt * 16);
        cp16(&fgB[s][tid], Bg + (size_t)kt * 256);
        asm volatile("cp.async.commit_group;");
    };

    issue(0, 0); issue(1, 1); issue(2, 2);

    for (int c = 0; c < nc; c++) {
        if (c <= nc - 3)      asm volatile("cp.async.wait_group 2;");
        else if (c == nc - 2) asm volatile("cp.async.wait_group 1;");
        else                  asm volatile("cp.async.wait_group 0;");
        __syncthreads();
        if (c + 3 < nc) issue((c + 3) & 3, c + 3);

        const int buf = c & 3;
        unsigned a[2][4];
        #pragma unroll
        for (int t = 0; t < 2; t++) {
            const __half* st = &stA[buf][(wm + t * 16 + g) * 24 + 2 * q];
            a[t][0] = *reinterpret_cast<const unsigned*>(st);
            a[t][1] = *reinterpret_cast<const unsigned*>(st + 8 * 24);
            a[t][2] = *reinterpret_cast<const unsigned*>(st + 8);
            a[t][3] = *reinterpret_cast<const unsigned*>(st + 8 * 24 + 8);
        }
        #pragma unroll
        for (int jp = 0; jp < 4; jp++) {
            const uint4 v = fgB[buf][((warp & 1) * 4 + jp) * 32 + lane];
            mmah(acc[0][jp * 2    ], a[0], v.x, v.y);
            mmah(acc[0][jp * 2 + 1], a[0], v.z, v.w);
            mmah(acc[1][jp * 2    ], a[1], v.x, v.y);
            mmah(acc[1][jp * 2 + 1], a[1], v.z, v.w);
        }
    }

    // epilogue
    #pragma unroll
    for (int t = 0; t < 2; t++) {
        const int m0 = bm0 + wm + t * 16 + g;
        const int m1 = m0 + 8;
        #pragma unroll
        for (int j = 0; j < 8; j++) {
            const int n0 = bn0 + wn + j * 8 + q * 2;
            const float b0 = bias[n0], b1 = bias[n0 + 1];
            float v00 = acc[t][j][0] + b0;
            float v01 = acc[t][j][1] + b1;
            float v10 = acc[t][j][2] + b0;
            float v11 = acc[t][j][3] + b1;
            if (MODE == EP_BIAS_GELU) {
                v00 = 0.5f * v00 * (1.f + erff(v00 * 0.70710678118654752f));
                v01 = 0.5f * v01 * (1.f + erff(v01 * 0.70710678118654752f));
                v10 = 0.5f * v10 * (1.f + erff(v10 * 0.70710678118654752f));
                v11 = 0.5f * v11 * (1.f + erff(v11 * 0.70710678118654752f));
            }
            if (MODE == EP_BIAS_RES) {
                const float2 r0 = *reinterpret_cast<const float2*>(R + (size_t)m0 * N + n0);
                const float2 r1 = *reinterpret_cast<const float2*>(R + (size_t)m1 * N + n0);
                v00 += r0.x; v01 += r0.y; v10 += r1.x; v11 += r1.y;
            }
            if (OUTH) {
                __half2* C = (__half2*)Cout;
                C[((size_t)m0 * N + n0) >> 1] = __floats2half2_rn(v00, v01);
                C[((size_t)m1 * N + n0) >> 1] = __floats2half2_rn(v10, v11);
            } else {
                float* C = (float*)Cout;
                *reinterpret_cast<float2*>(C + (size_t)m0 * N + n0) = make_float2(v00, v01);
                *reinterpret_cast<float2*>(C + (size_t)m1 * N + n0) = make_float2(v10, v11);
            }
        }
    }
}

// ---------------------------------------------------------------------------
// fused: atom-encoder SGEMM (x<6) + structural bias + graph-token fill (x>=6)
// ---------------------------------------------------------------------------
#define BM 128
#define BN 128
#define BK 8
#define TM 8
#define TN 8
#define XTRA 1538u   // extra grid.x slices: 1538*64*256 >= bias+fill elements

__global__ __launch_bounds__(256) void atom_fused_kernel(
    const float* __restrict__ A, const float* __restrict__ W,
    const float* __restrict__ bias_b, float* __restrict__ C,
    const int* __restrict__ len_spd, const float* __restrict__ spd_emb,
    const float* __restrict__ virt, const float* __restrict__ gt,
    float* __restrict__ bias)
{
    const int tid = threadIdx.x;

    if (blockIdx.x >= 6) {
        const size_t idx = ((size_t)(blockIdx.x - 6) * 64 + blockIdx.y) * 256 + tid;
        const size_t btot = (size_t)BATCH * NHEAD * NTOT * NTOT;
        if (idx < btot) {
            const int j = (int)(idx & 255);
            const int i = (int)((idx >> 8) & 255);
            const int hh = (int)((idx >> 16) % NHEAD);
            const int b = (int)(idx / ((size_t)NHEAD * NTOT * NTOT));
            float v;
            if (i == 0 || j == 0) {
                v = virt[hh];
            } else {
                const int lsp = len_spd[((size_t)b * NTOK + (i - 1)) * NTOK + (j - 1)];
                v = (lsp == 0) ? 0.f : spd_emb[lsp * NHEAD + hh];
            }
            bias[idx] = v;
        } else {
            const size_t r = idx - btot;
            if (r < (size_t)BATCH * HID) {
                const int b = (int)(r / HID), t = (int)(r % HID);
                C[(size_t)b * NTOT * HID + t] = gt[t];
            }
        }
        return;
    }

    __shared__ float As[BK][BM];
    __shared__ float Bs[BK][BN];

    const int bm0 = blockIdx.y * BM;
    const int bn0 = blockIdx.x * BN;
    const int tx = tid & 15;
    const int ty = tid >> 4;

    float acc[TM][TN];
    #pragma unroll
    for (int i = 0; i < TM; i++)
        #pragma unroll
        for (int j = 0; j < TN; j++) acc[i][j] = 0.f;

    const int arow = tid >> 1;
    const int acol = (tid & 1) * 4;
    const int brow = tid >> 5;
    const int bcol = (tid & 31) * 4;

    for (int k0 = 0; k0 < DIN; k0 += BK) {
        float4 av;
        const int gm = bm0 + arow;
        if (gm < MATOM)
            av = *reinterpret_cast<const float4*>(A + (size_t)gm * DIN + k0 + acol);
        else
            av = make_float4(0.f, 0.f, 0.f, 0.f);
        As[acol + 0][arow] = av.x;
        As[acol + 1][arow] = av.y;
        As[acol + 2][arow] = av.z;
        As[acol + 3][arow] = av.w;

        const float4 bv = *reinterpret_cast<const float4*>(
            W + (size_t)(k0 + brow) * HID + bn0 + bcol);
        *reinterpret_cast<float4*>(&Bs[brow][bcol]) = bv;

        __syncthreads();
        #pragma unroll
        for (int k = 0; k < BK; k++) {
            float af[TM], bf[TN];
            #pragma unroll
            for (int i = 0; i < TM; i++) af[i] = As[k][ty * TM + i];
            #pragma unroll
            for (int j = 0; j < TN; j++) bf[j] = Bs[k][tx * TN + j];
            #pragma unroll
            for (int i = 0; i < TM; i++)
                #pragma unroll
                for (int j = 0; j < TN; j++)
                    acc[i][j] = fmaf(af[i], bf[j], acc[i][j]);
        }
        __syncthreads();
    }

    #pragma unroll
    for (int i = 0; i < TM; i++) {
        const int m = bm0 + ty * TM + i;
        if (m >= MATOM) continue;
        const size_t orow = (size_t)m + (size_t)(m / NTOK) + 1;
        #pragma unroll
        for (int j = 0; j < TN; j++) {
            const int nn = bn0 + tx * TN + j;
            C[orow * HID + nn] = acc[i][j] + bias_b[nn];
        }
    }
}

// ---------------------------------------------------------------------------
// LayerNorm (templated output dtype)
// ---------------------------------------------------------------------------
template<bool OUTH>
__global__ __launch_bounds__(256) void ln_kernel(
    const float* __restrict__ X, const float* __restrict__ w,
    const float* __restrict__ b, void* __restrict__ Yout)
{
    const int row = blockIdx.x;
    const float* x = X + (size_t)row * HID;
    const int tid = threadIdx.x;

    float v0 = x[tid], v1 = x[tid + 256], v2 = x[tid + 512];
    float s = v0 + v1 + v2;

    __shared__ float red[8];
    #pragma unroll
    for (int o = 16; o > 0; o >>= 1) s += __shfl_xor_sync(~0u, s, o);
    if ((tid & 31) == 0) red[tid >> 5] = s;
    __syncthreads();
    float tot = red[0];
    #pragma unroll
    for (int wv = 1; wv < 8; wv++) tot += red[wv];
    const float mu = tot * (1.f / HID);
    __syncthreads();

    const float d0 = v0 - mu, d1 = v1 - mu, d2 = v2 - mu;
    float s2 = d0 * d0 + d1 * d1 + d2 * d2;
    #pragma unroll
    for (int o = 16; o > 0; o >>= 1) s2 += __shfl_xor_sync(~0u, s2, o);
    if ((tid & 31) == 0) red[tid >> 5] = s2;
    __syncthreads();
    float var = red[0];
    #pragma unroll
    for (int wv = 1; wv < 8; wv++) var += red[wv];
    var *= (1.f / HID);
    const float inv = rsqrtf(var + 1e-5f);

    const float y0 = d0 * inv * w[tid]       + b[tid];
    const float y1 = d1 * inv * w[tid + 256] + b[tid + 256];
    const float y2 = d2 * inv * w[tid + 512] + b[tid + 512];
    if (OUTH) {
        __half* Y = (__half*)Yout + (size_t)row * HID;
        Y[tid]       = __float2half_rn(y0);
        Y[tid + 256] = __float2half_rn(y1);
        Y[tid + 512] = __float2half_rn(y2);
    } else {
        float* Y = (float*)Yout + (size_t)row * HID;
        Y[tid] = y0; Y[tid + 256] = y1; Y[tid + 512] = y2;
    }
}

// ---------------------------------------------------------------------------
// Attention v2: warp-autonomous queries, fp16 K/V/Q, no CTA sync in main loop.
// Grid (NHEAD, BATCH), 256 thr. Warp w owns queries w*32..w*32+31.
// smem: Kh/Vh half2 [256][33] (stride 33 -> conflict-free), p-stage per warp.
// ---------------------------------------------------------------------------
#define AS2 33
#define ATTN_SMEM ((2 * 256 * AS2) * 4 + 8 * 256 * 4)

__global__ __launch_bounds__(256) void attn_kernel(
    const __half* __restrict__ Q, const __half* __restrict__ K,
    const __half* __restrict__ V, const float* __restrict__ bias,
    __half* __restrict__ O)
{
    extern __shared__ char smraw[];
    __half2* Kh = (__half2*)smraw;            // 256*33
    __half2* Vh = Kh + 256 * AS2;             // 256*33
    float*   ps = (float*)(Vh + 256 * AS2);   // 8*256

    const int h = blockIdx.x;
    const int b = blockIdx.y;
    const int tid = threadIdx.x;
    const int lane = tid & 31;
    const int warp = tid >> 5;

    const size_t base = (size_t)b * NTOT * HID + (size_t)h * HDIM;

    for (int idx = tid; idx < 256 * 32; idx += 256) {
        const int row = idx >> 5, c = idx & 31;
        Kh[row * AS2 + c] = reinterpret_cast<const __half2*>(K + base + (size_t)row * HID)[c];
        Vh[row * AS2 + c] = reinterpret_cast<const __half2*>(V + base + (size_t)row * HID)[c];
    }
    __syncthreads();

    const float* brow = bias + (((size_t)b * NHEAD + h) * NTOT) * NTOT;
    float* pw = ps + warp * 256;

    for (int t = 0; t < 32; t++) {
        const int qi = warp * 32 + t;
        const unsigned qbits = reinterpret_cast<const unsigned*>(Q + base + (size_t)qi * HID)[lane];

        float s[8];
        #pragma unroll
        for (int r = 0; r < 8; r++) s[r] = 0.f;

        #pragma unroll
        for (int c = 0; c < 32; c++) {
            const unsigned qb = __shfl_sync(~0u, qbits, c);
            __half2 qh = *reinterpret_cast<const __half2*>(&qb);
            const float2 qf = __half22float2(qh);
            #pragma unroll
            for (int r = 0; r < 8; r++) {
                const float2 kf = __half22float2(Kh[(lane + 32 * r) * AS2 + c]);
                s[r] = fmaf(qf.x, kf.x, fmaf(qf.y, kf.y, s[r]));
            }
        }

        float m = -1e30f;
        #pragma unroll
        for (int r = 0; r < 8; r++) {
            s[r] = s[r] * 0.125f + brow[(size_t)qi * NTOT + lane + 32 * r];
            m = fmaxf(m, s[r]);
        }
        #pragma unroll
        for (int o = 16; o > 0; o >>= 1) m = fmaxf(m, __shfl_xor_sync(~0u, m, o));

        float sum = 0.f;
        #pragma unroll
        for (int r = 0; r < 8; r++) {
            const float e = expf(s[r] - m);
            pw[lane + 32 * r] = e;
            sum += e;
        }
        #pragma unroll
        for (int o = 16; o > 0; o >>= 1) sum += __shfl_xor_sync(~0u, sum, o);
        const float inv = 1.f / sum;
        __syncwarp();

        float a0 = 0.f, a1 = 0.f;
        #pragma unroll 8
        for (int j = 0; j < 256; j++) {
            const float p = pw[j];
            const float2 vf = __half22float2(Vh[j * AS2 + lane]);
            a0 = fmaf(p, vf.x, a0);
            a1 = fmaf(p, vf.y, a1);
        }
        reinterpret_cast<__half2*>(O + base + (size_t)qi * HID)[lane] =
            __floats2half2_rn(a0 * inv, a1 * inv);
        __syncwarp();
    }
}

// ---------------------------------------------------------------------------
// Launch
// ---------------------------------------------------------------------------
extern "C" void kernel_launch(void* const* d_in, const int* in_sizes, int n_in,
                              void* d_out, int out_size)
{
    const float* x          = (const float*)d_in[0];
    const int*   len_spd    = (const int*)  d_in[1];
    const float* atom_W     = (const float*)d_in[2];
    const float* atom_b     = (const float*)d_in[3];
    const float* spd_emb    = (const float*)d_in[4];
    const float* graph_tok  = (const float*)d_in[5];
    const float* virt_dist  = (const float*)d_in[6];
    const float* ln1_w      = (const float*)d_in[7];
    const float* ln1_b      = (const float*)d_in[8];
    const float* Wq         = (const float*)d_in[9];
    const float* bq         = (const float*)d_in[10];
    const float* Wk         = (const float*)d_in[11];
    const float* bk         = (const float*)d_in[12];
    const float* Wv         = (const float*)d_in[13];
    const float* bv         = (const float*)d_in[14];
    const float* Wo         = (const float*)d_in[15];
    const float* bo         = (const float*)d_in[16];
    const float* ln2_w      = (const float*)d_in[17];
    const float* ln2_b      = (const float*)d_in[18];
    const float* W1         = (const float*)d_in[19];
    const float* b1         = (const float*)d_in[20];
    const float* W2         = (const float*)d_in[21];
    const float* b2         = (const float*)d_in[22];
    const float* fln_w      = (const float*)d_in[23];
    const float* fln_b      = (const float*)d_in[24];

    float *h, *bias;
    __half *yh, *qh, *kh, *vh, *oh, *fh, *wt;
    cudaGetSymbolAddress((void**)&h,    g_h);
    cudaGetSymbolAddress((void**)&yh,   g_yh);
    cudaGetSymbolAddress((void**)&qh,   g_qh);
    cudaGetSymbolAddress((void**)&kh,   g_kh);
    cudaGetSymbolAddress((void**)&vh,   g_vh);
    cudaGetSymbolAddress((void**)&oh,   g_oh);
    cudaGetSymbolAddress((void**)&fh,   g_fh);
    cudaGetSymbolAddress((void**)&bias, g_bias);
    cudaGetSymbolAddress((void**)&wt,   g_wt);

    cudaFuncSetAttribute(attn_kernel, cudaFuncAttributeMaxDynamicSharedMemorySize,
                         (int)ATTN_SMEM);

    const size_t szQ = (size_t)HID * HID, szF = (size_t)HID * FFN;

    const dim3 gQKV(18, MROWS / 128);
    const dim3 gHID(HID / 128, MROWS / 128);
    const dim3 gFFN(FFN / 128, MROWS / 128);

    // L1: repack QKVO weights (all layers)
    repack_qkvo_kernel<<<dim3((unsigned)(szQ / 2 / 256), 1, 4 * NLAYER), 256>>>(
        Wq, Wk, Wv, Wo, (__half2*)wt);
    // L2: fused atom encoder + bias + token fill
    atom_fused_kernel<<<dim3(6 + XTRA, 64), 256>>>(
        x, atom_W, atom_b, h, len_spd, spd_emb, virt_dist, graph_tok, bias);
    // L3: ln1 layer 0
    ln_kernel<true><<<MROWS, 256>>>(h, ln1_w, ln1_b, yh);
    // L4: QKV fused hgemm layer 0  <-- ncu capture slot
    hgemm_kernel<EP_BIAS, true, true><<<gQKV, 256>>>(
        yh, wt, bq, bk, bv, nullptr, qh, kh, vh, HID, HID);
    // L5: repack W1/W2 (needed from FFN1 of layer 0 onward)
    repack_w12_kernel<<<dim3((unsigned)(szF / 2 / 256), 1, 2 * NLAYER), 256>>>(
        W1, W2, (__half2*)wt);

    for (int l = 0; l < NLAYER; l++) {
        const size_t bofs  = (size_t)l * HID;
        const size_t b1ofs = (size_t)l * FFN;
        __half* wl = wt + (size_t)l * WT_L;

        if (l > 0) {
            ln_kernel<true><<<MROWS, 256>>>(h, ln1_w + bofs, ln1_b + bofs, yh);
            hgemm_kernel<EP_BIAS, true, true><<<gQKV, 256>>>(
                yh, wl, bq + bofs, bk + bofs, bv + bofs, nullptr,
                qh, kh, vh, HID, HID);
        }

        attn_kernel<<<dim3(NHEAD, BATCH), 256, ATTN_SMEM>>>(qh, kh, vh, bias, oh);

        hgemm_kernel<EP_BIAS_RES, false, false><<<gHID, 256>>>(
            oh, wl + 3 * (size_t)WT_QKVO, bo + bofs, nullptr, nullptr, h,
            h, nullptr, nullptr, HID, HID);

        ln_kernel<true><<<MROWS, 256>>>(h, ln2_w + bofs, ln2_b + bofs, yh);

        hgemm_kernel<EP_BIAS_GELU, true, false><<<gFFN, 256>>>(
            yh, wl + 4 * (size_t)WT_QKVO, b1 + b1ofs, nullptr, nullptr, nullptr,
            fh, nullptr, nullptr, HID, FFN);
        hgemm_kernel<EP_BIAS_RES, false, false><<<gHID, 256>>>(
            fh, wl + 4 * (size_t)WT_QKVO + szF, b2 + bofs, nullptr, nullptr, h,
            h, nullptr, nullptr, FFN, HID);
    }

    ln_kernel<false><<<MROWS, 256>>>(h, fln_w, fln_b, d_out);
}

// round 11
// speedup vs baseline: 4.4761x; 1.4594x over previous
#include <cuda_runtime.h>
#include <cuda_fp16.h>
#include <math.h>
#include <stdint.h>

// ---------------------------------------------------------------------------
// Problem constants
// ---------------------------------------------------------------------------
#define BATCH   32
#define NTOK    255
#define NTOT    256
#define DIN     64
#define NHEAD   12
#define HID     768
#define FFN     3072
#define NLAYER  6
#define HDIM    64
#define MROWS   (BATCH*NTOT) // 8192
#define MATOM   (BATCH*NTOK) // 8160

// ---------------------------------------------------------------------------
// Scratch (device globals; no allocations allowed)
// ---------------------------------------------------------------------------
__device__ __align__(256) float  g_h  [(size_t)MROWS*HID];
__device__ __align__(256) __half g_yh [(size_t)MROWS*HID];
__device__ __align__(256) __half g_qh [(size_t)MROWS*HID];
__device__ __align__(256) __half g_kh [(size_t)MROWS*HID];
__device__ __align__(256) __half g_vh [(size_t)MROWS*HID];
__device__ __align__(256) __half g_oh [(size_t)MROWS*HID];
__device__ __align__(256) __half g_fh [(size_t)MROWS*FFN];
__device__ __align__(256) float  g_bias[(size_t)BATCH*NHEAD*NTOT*NTOT];

// fragment-packed fp16 weights (per layer: Wq,Wk,Wv,Wo,W1,W2 contiguous)
#define WT_QKVO (HID*HID)                  // halves
#define WT_L    (4*WT_QKVO + 2*HID*FFN)    // halves per layer
__device__ __align__(256) __half g_wt[(size_t)NLAYER*WT_L];

enum { EP_BIAS = 0, EP_BIAS_RES = 1, EP_BIAS_GELU = 2 };

// ---------------------------------------------------------------------------
// helpers
// ---------------------------------------------------------------------------
__device__ __forceinline__ void cp16(void* smem, const void* gmem) {
    unsigned s = (unsigned)__cvta_generic_to_shared(smem);
    asm volatile("cp.async.cg.shared.global [%0], [%1], 16;" :: "r"(s), "l"(gmem));
}
__device__ __forceinline__ void mmah(float c[4], const unsigned a[4],
                                     unsigned b0, unsigned b1) {
    asm volatile(
        "mma.sync.aligned.m16n8k16.row.col.f32.f16.f16.f32 "
        "{%0,%1,%2,%3}, {%4,%5,%6,%7}, {%8,%9}, {%0,%1,%2,%3};"
        : "+f"(c[0]), "+f"(c[1]), "+f"(c[2]), "+f"(c[3])
        : "r"(a[0]), "r"(a[1]), "r"(a[2]), "r"(a[3]), "r"(b0), "r"(b1));
}

// ---------------------------------------------------------------------------
// Weight repack: W[K][N] fp32 -> fragment-ordered fp16 half2 (per matrix)
// ---------------------------------------------------------------------------
__device__ __forceinline__ void repack_one(
    const float* __restrict__ in, __half2* __restrict__ out,
    unsigned idx, int N, int ktiles)
{
    const int c    = idx & 3;
    const int lane = (idx >> 2) & 31;
    const int p    = (idx >> 7) & 7;
    const unsigned rest = idx >> 10;
    const int kt = (int)(rest % (unsigned)ktiles);
    const int nt = (int)(rest / (unsigned)ktiles);
    const int g = lane >> 2, q = lane & 3;
    const int k = kt * 16 + (c & 1) * 8 + q * 2;
    const int n = nt * 128 + (p * 2 + (c >> 1)) * 8 + g;
    out[idx] = __floats2half2_rn(in[(size_t)k * N + n], in[(size_t)(k + 1) * N + n]);
}

__global__ __launch_bounds__(256) void repack_qkvo_kernel(
    const float* __restrict__ Wq, const float* __restrict__ Wk,
    const float* __restrict__ Wv, const float* __restrict__ Wo,
    __half2* __restrict__ wt)
{
    const int z = blockIdx.z, type = z & 3, layer = z >> 2;
    const float* ins[4] = { Wq, Wk, Wv, Wo };
    const float* in = ins[type] + (size_t)layer * HID * HID;
    __half2* out = wt + ((size_t)layer * WT_L + (size_t)type * WT_QKVO) / 2;
    repack_one(in, out, blockIdx.x * 256u + threadIdx.x, HID, HID / 16);
}

__global__ __launch_bounds__(256) void repack_w12_kernel(
    const float* __restrict__ W1, const float* __restrict__ W2,
    __half2* __restrict__ wt)
{
    const int z = blockIdx.z;
    const size_t szF = (size_t)HID * FFN;
    const unsigned idx = blockIdx.x * 256u + threadIdx.x;
    if (z < NLAYER) {
        const float* in = W1 + (size_t)z * szF;
        __half2* out = wt + ((size_t)z * WT_L + 4 * (size_t)WT_QKVO) / 2;
        repack_one(in, out, idx, FFN, HID / 16);
    } else {
        const int layer = z - NLAYER;
        const float* in = W2 + (size_t)layer * szF;
        __half2* out = wt + ((size_t)layer * WT_L + 4 * (size_t)WT_QKVO + szF) / 2;
        repack_one(in, out, idx, HID, FFN / 16);
    }
}

// ---------------------------------------------------------------------------
// fp16 mma.sync GEMM, 4-stage cp.async pipeline, 1 sync/iter (unchanged).
// ---------------------------------------------------------------------------
template<int MODE, bool OUTH, bool QKV>
__global__ __launch_bounds__(256, 2) void hgemm_kernel(
    const __half* __restrict__ A, const __half* __restrict__ Wpk,
    const float* __restrict__ bias0, const float* __restrict__ bias1,
    const float* __restrict__ bias2, const float* __restrict__ R,
    void* __restrict__ C0, void* __restrict__ C1, void* __restrict__ C2,
    int K, int N)
{
    __shared__ __half stA[4][128 * 24];
    __shared__ uint4  fgB[4][256];

    const int tid  = threadIdx.x;
    const int lane = tid & 31;
    const int warp = tid >> 5;
    const int g    = lane >> 2;
    const int q    = lane & 3;
    const int bm0  = blockIdx.y * 128;
    const int wn   = (warp & 1) * 64;
    const int wm   = (warp >> 1) * 32;

    int bn0 = blockIdx.x * 128;
    const float* bias = bias0;
    void* Cout = C0;
    if (QKV) {
        const int type = blockIdx.x / 6;         // 0=q 1=k 2=v
        bn0 -= type * 768;
        bias = (type == 0) ? bias0 : (type == 1 ? bias1 : bias2);
        Cout = (type == 0) ? C0 : (type == 1 ? C1 : C2);
    }

    const int nc = K / 16;
    const __half* Ag = A + (size_t)(bm0 + (tid >> 1)) * K + (tid & 1) * 8;
    const uint4*  Bg = reinterpret_cast<const uint4*>(Wpk)
                       + (size_t)blockIdx.x * nc * 256 + tid;
    const int saOfs = (tid >> 1) * 24 + (tid & 1) * 8;

    float acc[2][8][4];
    #pragma unroll
    for (int t = 0; t < 2; t++)
        #pragma unroll
        for (int j = 0; j < 8; j++)
            #pragma unroll
            for (int r = 0; r < 4; r++) acc[t][j][r] = 0.f;

    auto issue = [&](int s, int kt) {
        cp16(&stA[s][saOfs], Ag + kt * 16);
        cp16(&fgB[s][tid], Bg + (size_t)kt * 256);
        asm volatile("cp.async.commit_group;");
    };

    issue(0, 0); issue(1, 1); issue(2, 2);

    for (int c = 0; c < nc; c++) {
        if (c <= nc - 3)      asm volatile("cp.async.wait_group 2;");
        else if (c == nc - 2) asm volatile("cp.async.wait_group 1;");
        else                  asm volatile("cp.async.wait_group 0;");
        __syncthreads();
        if (c + 3 < nc) issue((c + 3) & 3, c + 3);

        const int buf = c & 3;
        unsigned a[2][4];
        #pragma unroll
        for (int t = 0; t < 2; t++) {
            const __half* st = &stA[buf][(wm + t * 16 + g) * 24 + 2 * q];
            a[t][0] = *reinterpret_cast<const unsigned*>(st);
            a[t][1] = *reinterpret_cast<const unsigned*>(st + 8 * 24);
            a[t][2] = *reinterpret_cast<const unsigned*>(st + 8);
            a[t][3] = *reinterpret_cast<const unsigned*>(st + 8 * 24 + 8);
        }
        #pragma unroll
        for (int jp = 0; jp < 4; jp++) {
            const uint4 v = fgB[buf][((warp & 1) * 4 + jp) * 32 + lane];
            mmah(acc[0][jp * 2    ], a[0], v.x, v.y);
            mmah(acc[0][jp * 2 + 1], a[0], v.z, v.w);
            mmah(acc[1][jp * 2    ], a[1], v.x, v.y);
            mmah(acc[1][jp * 2 + 1], a[1], v.z, v.w);
        }
    }

    // epilogue
    #pragma unroll
    for (int t = 0; t < 2; t++) {
        const int m0 = bm0 + wm + t * 16 + g;
        const int m1 = m0 + 8;
        #pragma unroll
        for (int j = 0; j < 8; j++) {
            const int n0 = bn0 + wn + j * 8 + q * 2;
            const float b0 = bias[n0], b1 = bias[n0 + 1];
            float v00 = acc[t][j][0] + b0;
            float v01 = acc[t][j][1] + b1;
            float v10 = acc[t][j][2] + b0;
            float v11 = acc[t][j][3] + b1;
            if (MODE == EP_BIAS_GELU) {
                v00 = 0.5f * v00 * (1.f + erff(v00 * 0.70710678118654752f));
                v01 = 0.5f * v01 * (1.f + erff(v01 * 0.70710678118654752f));
                v10 = 0.5f * v10 * (1.f + erff(v10 * 0.70710678118654752f));
                v11 = 0.5f * v11 * (1.f + erff(v11 * 0.70710678118654752f));
            }
            if (MODE == EP_BIAS_RES) {
                const float2 r0 = *reinterpret_cast<const float2*>(R + (size_t)m0 * N + n0);
                const float2 r1 = *reinterpret_cast<const float2*>(R + (size_t)m1 * N + n0);
                v00 += r0.x; v01 += r0.y; v10 += r1.x; v11 += r1.y;
            }
            if (OUTH) {
                __half2* C = (__half2*)Cout;
                C[((size_t)m0 * N + n0) >> 1] = __floats2half2_rn(v00, v01);
                C[((size_t)m1 * N + n0) >> 1] = __floats2half2_rn(v10, v11);
            } else {
                float* C = (float*)Cout;
                *reinterpret_cast<float2*>(C + (size_t)m0 * N + n0) = make_float2(v00, v01);
                *reinterpret_cast<float2*>(C + (size_t)m1 * N + n0) = make_float2(v10, v11);
            }
        }
    }
}

// ---------------------------------------------------------------------------
// fused: atom-encoder SGEMM (x<6) + structural bias + graph-token fill (x>=6)
// ---------------------------------------------------------------------------
#define BM 128
#define BN 128
#define BK 8
#define TM 8
#define TN 8
#define XTRA 1538u

__global__ __launch_bounds__(256) void atom_fused_kernel(
    const float* __restrict__ A, const float* __restrict__ W,
    const float* __restrict__ bias_b, float* __restrict__ C,
    const int* __restrict__ len_spd, const float* __restrict__ spd_emb,
    const float* __restrict__ virt, const float* __restrict__ gt,
    float* __restrict__ bias)
{
    const int tid = threadIdx.x;

    if (blockIdx.x >= 6) {
        const size_t idx = ((size_t)(blockIdx.x - 6) * 64 + blockIdx.y) * 256 + tid;
        const size_t btot = (size_t)BATCH * NHEAD * NTOT * NTOT;
        if (idx < btot) {
            const int j = (int)(idx & 255);
            const int i = (int)((idx >> 8) & 255);
            const int hh = (int)((idx >> 16) % NHEAD);
            const int b = (int)(idx / ((size_t)NHEAD * NTOT * NTOT));
            float v;
            if (i == 0 || j == 0) {
                v = virt[hh];
            } else {
                const int lsp = len_spd[((size_t)b * NTOK + (i - 1)) * NTOK + (j - 1)];
                v = (lsp == 0) ? 0.f : spd_emb[lsp * NHEAD + hh];
            }
            bias[idx] = v;
        } else {
            const size_t r = idx - btot;
            if (r < (size_t)BATCH * HID) {
                const int b = (int)(r / HID), t = (int)(r % HID);
                C[(size_t)b * NTOT * HID + t] = gt[t];
            }
        }
        return;
    }

    __shared__ float As[BK][BM];
    __shared__ float Bs[BK][BN];

    const int bm0 = blockIdx.y * BM;
    const int bn0 = blockIdx.x * BN;
    const int tx = tid & 15;
    const int ty = tid >> 4;

    float acc[TM][TN];
    #pragma unroll
    for (int i = 0; i < TM; i++)
        #pragma unroll
        for (int j = 0; j < TN; j++) acc[i][j] = 0.f;

    const int arow = tid >> 1;
    const int acol = (tid & 1) * 4;
    const int brow = tid >> 5;
    const int bcol = (tid & 31) * 4;

    for (int k0 = 0; k0 < DIN; k0 += BK) {
        float4 av;
        const int gm = bm0 + arow;
        if (gm < MATOM)
            av = *reinterpret_cast<const float4*>(A + (size_t)gm * DIN + k0 + acol);
        else
            av = make_float4(0.f, 0.f, 0.f, 0.f);
        As[acol + 0][arow] = av.x;
        As[acol + 1][arow] = av.y;
        As[acol + 2][arow] = av.z;
        As[acol + 3][arow] = av.w;

        const float4 bv = *reinterpret_cast<const float4*>(
            W + (size_t)(k0 + brow) * HID + bn0 + bcol);
        *reinterpret_cast<float4*>(&Bs[brow][bcol]) = bv;

        __syncthreads();
        #pragma unroll
        for (int k = 0; k < BK; k++) {
            float af[TM], bf[TN];
            #pragma unroll
            for (int i = 0; i < TM; i++) af[i] = As[k][ty * TM + i];
            #pragma unroll
            for (int j = 0; j < TN; j++) bf[j] = Bs[k][tx * TN + j];
            #pragma unroll
            for (int i = 0; i < TM; i++)
                #pragma unroll
                for (int j = 0; j < TN; j++)
                    acc[i][j] = fmaf(af[i], bf[j], acc[i][j]);
        }
        __syncthreads();
    }

    #pragma unroll
    for (int i = 0; i < TM; i++) {
        const int m = bm0 + ty * TM + i;
        if (m >= MATOM) continue;
        const size_t orow = (size_t)m + (size_t)(m / NTOK) + 1;
        #pragma unroll
        for (int j = 0; j < TN; j++) {
            const int nn = bn0 + tx * TN + j;
            C[orow * HID + nn] = acc[i][j] + bias_b[nn];
        }
    }
}

// ---------------------------------------------------------------------------
// LayerNorm (templated output dtype)
// ---------------------------------------------------------------------------
template<bool OUTH>
__global__ __launch_bounds__(256) void ln_kernel(
    const float* __restrict__ X, const float* __restrict__ w,
    const float* __restrict__ b, void* __restrict__ Yout)
{
    const int row = blockIdx.x;
    const float* x = X + (size_t)row * HID;
    const int tid = threadIdx.x;

    float v0 = x[tid], v1 = x[tid + 256], v2 = x[tid + 512];
    float s = v0 + v1 + v2;

    __shared__ float red[8];
    #pragma unroll
    for (int o = 16; o > 0; o >>= 1) s += __shfl_xor_sync(~0u, s, o);
    if ((tid & 31) == 0) red[tid >> 5] = s;
    __syncthreads();
    float tot = red[0];
    #pragma unroll
    for (int wv = 1; wv < 8; wv++) tot += red[wv];
    const float mu = tot * (1.f / HID);
    __syncthreads();

    const float d0 = v0 - mu, d1 = v1 - mu, d2 = v2 - mu;
    float s2 = d0 * d0 + d1 * d1 + d2 * d2;
    #pragma unroll
    for (int o = 16; o > 0; o >>= 1) s2 += __shfl_xor_sync(~0u, s2, o);
    if ((tid & 31) == 0) red[tid >> 5] = s2;
    __syncthreads();
    float var = red[0];
    #pragma unroll
    for (int wv = 1; wv < 8; wv++) var += red[wv];
    var *= (1.f / HID);
    const float inv = rsqrtf(var + 1e-5f);

    const float y0 = d0 * inv * w[tid]       + b[tid];
    const float y1 = d1 * inv * w[tid + 256] + b[tid + 256];
    const float y2 = d2 * inv * w[tid + 512] + b[tid + 512];
    if (OUTH) {
        __half* Y = (__half*)Yout + (size_t)row * HID;
        Y[tid]       = __float2half_rn(y0);
        Y[tid + 256] = __float2half_rn(y1);
        Y[tid + 512] = __float2half_rn(y2);
    } else {
        float* Y = (float*)Yout + (size_t)row * HID;
        Y[tid] = y0; Y[tid + 256] = y1; Y[tid + 512] = y2;
    }
}

// ---------------------------------------------------------------------------
// Attention v3: tensor-core MMA. One CTA per (b,h), 8 warps, 2 passes of 128
// queries; each warp owns an m16 query tile. S acc + softmax + P pack all in
// registers; P fragments feed AV MMA directly (S-acc layout == A-frag layout).
// ---------------------------------------------------------------------------
#define KT_S 264   // half2 stride: KT[32][264]
#define VT_S 72    // half2 stride: VT[128][72]
#define QS_S 36    // half2 stride: QS[128][36]
#define ATTN_SMEM ((32*KT_S + 128*VT_S + 128*QS_S) * 4)

__global__ __launch_bounds__(256, 1) void attn_kernel(
    const __half* __restrict__ Q, const __half* __restrict__ K,
    const __half* __restrict__ V, const float* __restrict__ bias,
    __half* __restrict__ O)
{
    extern __shared__ char smraw[];
    __half2* KT = (__half2*)smraw;           // [k2=32][n=256] : half2(K[n][2k2],K[n][2k2+1])
    __half2* VT = KT + 32 * KT_S;            // [t2=128][d=64] : half2(V[2t2][d],V[2t2+1][d])
    __half2* QS = VT + 128 * VT_S;           // [r=128][k2=32]

    const int h = blockIdx.x, b = blockIdx.y;
    const int tid = threadIdx.x, lane = tid & 31, warp = tid >> 5;
    const int g = lane >> 2, q = lane & 3;
    const size_t base = (size_t)b * NTOT * HID + (size_t)h * HDIM;

    for (int i = tid; i < 8192; i += 256) {
        const int n = i >> 5, k2 = i & 31;
        KT[k2 * KT_S + n] =
            reinterpret_cast<const __half2*>(K + base + (size_t)n * HID)[k2];
    }
    for (int i = tid; i < 8192; i += 256) {
        const int t2 = i >> 6, d = i & 63;
        VT[t2 * VT_S + d] = __halves2half2(V[base + (size_t)(2 * t2) * HID + d],
                                           V[base + (size_t)(2 * t2 + 1) * HID + d]);
    }

    const float* bb = bias + (((size_t)b * NHEAD + h) * NTOT) * NTOT;

    for (int pass = 0; pass < 2; pass++) {
        __syncthreads();
        for (int i = tid; i < 4096; i += 256) {
            const int r = i >> 5, k2 = i & 31;
            QS[r * QS_S + k2] = reinterpret_cast<const __half2*>(
                Q + base + (size_t)(pass * 128 + r) * HID)[k2];
        }
        __syncthreads();

        const int r0 = warp * 16;
        float sc[32][4];
        #pragma unroll
        for (int j = 0; j < 32; j++) {
            sc[j][0] = sc[j][1] = sc[j][2] = sc[j][3] = 0.f;
        }

        // S = Q K^T  (M=16, N=256, K=64)
        #pragma unroll
        for (int kt = 0; kt < 4; kt++) {
            unsigned a[4];
            a[0] = *reinterpret_cast<const unsigned*>(&QS[(r0 + g    ) * QS_S + q + 8 * kt]);
            a[1] = *reinterpret_cast<const unsigned*>(&QS[(r0 + g + 8) * QS_S + q + 8 * kt]);
            a[2] = *reinterpret_cast<const unsigned*>(&QS[(r0 + g    ) * QS_S + q + 4 + 8 * kt]);
            a[3] = *reinterpret_cast<const unsigned*>(&QS[(r0 + g + 8) * QS_S + q + 4 + 8 * kt]);
            #pragma unroll
            for (int j = 0; j < 32; j++) {
                const unsigned b0 = *reinterpret_cast<const unsigned*>(
                    &KT[(8 * kt + q    ) * KT_S + j * 8 + g]);
                const unsigned b1 = *reinterpret_cast<const unsigned*>(
                    &KT[(8 * kt + 4 + q) * KT_S + j * 8 + g]);
                mmah(sc[j], a, b0, b1);
            }
        }

        const int qi0 = pass * 128 + r0 + g;
        const int qi1 = qi0 + 8;
        const float* b0r = bb + (size_t)qi0 * NTOT;
        const float* b1r = bb + (size_t)qi1 * NTOT;

        float m0 = -1e30f, m1 = -1e30f;
        #pragma unroll
        for (int j = 0; j < 32; j++) {
            const float2 bg0 = *reinterpret_cast<const float2*>(&b0r[j * 8 + 2 * q]);
            const float2 bg1 = *reinterpret_cast<const float2*>(&b1r[j * 8 + 2 * q]);
            sc[j][0] = sc[j][0] * 0.125f + bg0.x;
            sc[j][1] = sc[j][1] * 0.125f + bg0.y;
            sc[j][2] = sc[j][2] * 0.125f + bg1.x;
            sc[j][3] = sc[j][3] * 0.125f + bg1.y;
            m0 = fmaxf(m0, fmaxf(sc[j][0], sc[j][1]));
            m1 = fmaxf(m1, fmaxf(sc[j][2], sc[j][3]));
        }
        m0 = fmaxf(m0, __shfl_xor_sync(~0u, m0, 1));
        m0 = fmaxf(m0, __shfl_xor_sync(~0u, m0, 2));
        m1 = fmaxf(m1, __shfl_xor_sync(~0u, m1, 1));
        m1 = fmaxf(m1, __shfl_xor_sync(~0u, m1, 2));

        float s0 = 0.f, s1 = 0.f;
        unsigned p0[32], p1[32];
        #pragma unroll
        for (int j = 0; j < 32; j++) {
            const float e0 = expf(sc[j][0] - m0), e1 = expf(sc[j][1] - m0);
            const float e2 = expf(sc[j][2] - m1), e3 = expf(sc[j][3] - m1);
            s0 += e0 + e1; s1 += e2 + e3;
            const __half2 h0 = __floats2half2_rn(e0, e1);
            const __half2 h1 = __floats2half2_rn(e2, e3);
            p0[j] = *reinterpret_cast<const unsigned*>(&h0);
            p1[j] = *reinterpret_cast<const unsigned*>(&h1);
        }
        s0 += __shfl_xor_sync(~0u, s0, 1); s0 += __shfl_xor_sync(~0u, s0, 2);
        s1 += __shfl_xor_sync(~0u, s1, 1); s1 += __shfl_xor_sync(~0u, s1, 2);
        const float i0 = 1.f / s0, i1 = 1.f / s1;

        // O = P V  (M=16, N=64, K=256); A-frags taken directly from p0/p1.
        float av[8][4];
        #pragma unroll
        for (int j = 0; j < 8; j++) {
            av[j][0] = av[j][1] = av[j][2] = av[j][3] = 0.f;
        }
        #pragma unroll
        for (int kt = 0; kt < 16; kt++) {
            const unsigned a[4] = { p0[2 * kt], p1[2 * kt], p0[2 * kt + 1], p1[2 * kt + 1] };
            #pragma unroll
            for (int j = 0; j < 8; j++) {
                const unsigned vb0 = *reinterpret_cast<const unsigned*>(
                    &VT[(8 * kt + q    ) * VT_S + j * 8 + g]);
                const unsigned vb1 = *reinterpret_cast<const unsigned*>(
                    &VT[(8 * kt + 4 + q) * VT_S + j * 8 + g]);
                mmah(av[j], a, vb0, vb1);
            }
        }

        __half2* O0 = reinterpret_cast<__half2*>(O + base + (size_t)qi0 * HID);
        __half2* O1 = reinterpret_cast<__half2*>(O + base + (size_t)qi1 * HID);
        #pragma unroll
        for (int j = 0; j < 8; j++) {
            O0[j * 4 + q] = __floats2half2_rn(av[j][0] * i0, av[j][1] * i0);
            O1[j * 4 + q] = __floats2half2_rn(av[j][2] * i1, av[j][3] * i1);
        }
    }
}

// ---------------------------------------------------------------------------
// Launch
// ---------------------------------------------------------------------------
extern "C" void kernel_launch(void* const* d_in, const int* in_sizes, int n_in,
                              void* d_out, int out_size)
{
    const float* x          = (const float*)d_in[0];
    const int*   len_spd    = (const int*)  d_in[1];
    const float* atom_W     = (const float*)d_in[2];
    const float* atom_b     = (const float*)d_in[3];
    const float* spd_emb    = (const float*)d_in[4];
    const float* graph_tok  = (const float*)d_in[5];
    const float* virt_dist  = (const float*)d_in[6];
    const float* ln1_w      = (const float*)d_in[7];
    const float* ln1_b      = (const float*)d_in[8];
    const float* Wq         = (const float*)d_in[9];
    const float* bq         = (const float*)d_in[10];
    const float* Wk         = (const float*)d_in[11];
    const float* bk         = (const float*)d_in[12];
    const float* Wv         = (const float*)d_in[13];
    const float* bv         = (const float*)d_in[14];
    const float* Wo         = (const float*)d_in[15];
    const float* bo         = (const float*)d_in[16];
    const float* ln2_w      = (const float*)d_in[17];
    const float* ln2_b      = (const float*)d_in[18];
    const float* W1         = (const float*)d_in[19];
    const float* b1         = (const float*)d_in[20];
    const float* W2         = (const float*)d_in[21];
    const float* b2         = (const float*)d_in[22];
    const float* fln_w      = (const float*)d_in[23];
    const float* fln_b      = (const float*)d_in[24];

    float *h, *bias;
    __half *yh, *qh, *kh, *vh, *oh, *fh, *wt;
    cudaGetSymbolAddress((void**)&h,    g_h);
    cudaGetSymbolAddress((void**)&yh,   g_yh);
    cudaGetSymbolAddress((void**)&qh,   g_qh);
    cudaGetSymbolAddress((void**)&kh,   g_kh);
    cudaGetSymbolAddress((void**)&vh,   g_vh);
    cudaGetSymbolAddress((void**)&oh,   g_oh);
    cudaGetSymbolAddress((void**)&fh,   g_fh);
    cudaGetSymbolAddress((void**)&bias, g_bias);
    cudaGetSymbolAddress((void**)&wt,   g_wt);

    cudaFuncSetAttribute(attn_kernel, cudaFuncAttributeMaxDynamicSharedMemorySize,
                         (int)ATTN_SMEM);

    const size_t szQ = (size_t)HID * HID, szF = (size_t)HID * FFN;

    const dim3 gQKV(18, MROWS / 128);
    const dim3 gHID(HID / 128, MROWS / 128);
    const dim3 gFFN(FFN / 128, MROWS / 128);

    // L1: repack QKVO weights (all layers)
    repack_qkvo_kernel<<<dim3((unsigned)(szQ / 2 / 256), 1, 4 * NLAYER), 256>>>(
        Wq, Wk, Wv, Wo, (__half2*)wt);
    // L2: fused atom encoder + bias + token fill
    atom_fused_kernel<<<dim3(6 + XTRA, 64), 256>>>(
        x, atom_W, atom_b, h, len_spd, spd_emb, virt_dist, graph_tok, bias);
    // L3: ln1 layer 0
    ln_kernel<true><<<MROWS, 256>>>(h, ln1_w, ln1_b, yh);
    // L4: QKV fused hgemm layer 0  <-- ncu capture slot
    hgemm_kernel<EP_BIAS, true, true><<<gQKV, 256>>>(
        yh, wt, bq, bk, bv, nullptr, qh, kh, vh, HID, HID);
    // L5: repack W1/W2
    repack_w12_kernel<<<dim3((unsigned)(szF / 2 / 256), 1, 2 * NLAYER), 256>>>(
        W1, W2, (__half2*)wt);

    for (int l = 0; l < NLAYER; l++) {
        const size_t bofs  = (size_t)l * HID;
        const size_t b1ofs = (size_t)l * FFN;
        __half* wl = wt + (size_t)l * WT_L;

        if (l > 0) {
            ln_kernel<true><<<MROWS, 256>>>(h, ln1_w + bofs, ln1_b + bofs, yh);
            hgemm_kernel<EP_BIAS, true, true><<<gQKV, 256>>>(
                yh, wl, bq + bofs, bk + bofs, bv + bofs, nullptr,
                qh, kh, vh, HID, HID);
        }

        attn_kernel<<<dim3(NHEAD, BATCH), 256, ATTN_SMEM>>>(qh, kh, vh, bias, oh);

        hgemm_kernel<EP_BIAS_RES, false, false><<<gHID, 256>>>(
            oh, wl + 3 * (size_t)WT_QKVO, bo + bofs, nullptr, nullptr, h,
            h, nullptr, nullptr, HID, HID);

        ln_kernel<true><<<MROWS, 256>>>(h, ln2_w + bofs, ln2_b + bofs, yh);

        hgemm_kernel<EP_BIAS_GELU, true, false><<<gFFN, 256>>>(
            yh, wl + 4 * (size_t)WT_QKVO, b1 + b1ofs, nullptr, nullptr, nullptr,
            fh, nullptr, nullptr, HID, FFN);
        hgemm_kernel<EP_BIAS_RES, false, false><<<gHID, 256>>>(
            fh, wl + 4 * (size_t)WT_QKVO + szF, b2 + bofs, nullptr, nullptr, h,
            h, nullptr, nullptr, FFN, HID);
    }

    ln_kernel<false><<<MROWS, 256>>>(h, fln_w, fln_b, d_out);
}

// round 12
// speedup vs baseline: 4.5563x; 1.0179x over previous
#include <cuda_runtime.h>
#include <cuda_fp16.h>
#include <math.h>
#include <stdint.h>

// ---------------------------------------------------------------------------
// Problem constants
// ---------------------------------------------------------------------------
#define BATCH   32
#define NTOK    255
#define NTOT    256
#define DIN     64
#define NHEAD   12
#define HID     768
#define FFN     3072
#define NLAYER  6
#define HDIM    64
#define MROWS   (BATCH*NTOT) // 8192
#define MATOM   (BATCH*NTOK) // 8160

// ---------------------------------------------------------------------------
// Scratch (device globals; no allocations allowed)
// ---------------------------------------------------------------------------
__device__ __align__(256) float  g_h  [(size_t)MROWS*HID];
__device__ __align__(256) __half g_yh [(size_t)MROWS*HID];
__device__ __align__(256) __half g_qh [(size_t)MROWS*HID];
__device__ __align__(256) __half g_kh [(size_t)MROWS*HID];
__device__ __align__(256) __half g_vh [(size_t)MROWS*HID];
__device__ __align__(256) __half g_oh [(size_t)MROWS*HID];
__device__ __align__(256) __half g_fh [(size_t)MROWS*FFN];
__device__ __align__(256) float  g_bias[(size_t)BATCH*NHEAD*NTOT*NTOT];

// fragment-packed fp16 weights (per layer: Wq,Wk,Wv,Wo,W1,W2 contiguous)
#define WT_QKVO (HID*HID)                  // halves
#define WT_L    (4*WT_QKVO + 2*HID*FFN)    // halves per layer
__device__ __align__(256) __half g_wt[(size_t)NLAYER*WT_L];

enum { EP_BIAS = 0, EP_BIAS_RES = 1, EP_BIAS_GELU = 2 };

// ---------------------------------------------------------------------------
// helpers
// ---------------------------------------------------------------------------
__device__ __forceinline__ void cp16(void* smem, const void* gmem) {
    unsigned s = (unsigned)__cvta_generic_to_shared(smem);
    asm volatile("cp.async.cg.shared.global [%0], [%1], 16;" :: "r"(s), "l"(gmem));
}
__device__ __forceinline__ void mmah(float c[4], const unsigned a[4],
                                     unsigned b0, unsigned b1) {
    asm volatile(
        "mma.sync.aligned.m16n8k16.row.col.f32.f16.f16.f32 "
        "{%0,%1,%2,%3}, {%4,%5,%6,%7}, {%8,%9}, {%0,%1,%2,%3};"
        : "+f"(c[0]), "+f"(c[1]), "+f"(c[2]), "+f"(c[3])
        : "r"(a[0]), "r"(a[1]), "r"(a[2]), "r"(a[3]), "r"(b0), "r"(b1));
}

// ---------------------------------------------------------------------------
// Weight repack: W[K][N] fp32 -> fragment-ordered fp16 half2 (per matrix)
// ---------------------------------------------------------------------------
__device__ __forceinline__ void repack_one(
    const float* __restrict__ in, __half2* __restrict__ out,
    unsigned idx, int N, int ktiles)
{
    const int c    = idx & 3;
    const int lane = (idx >> 2) & 31;
    const int p    = (idx >> 7) & 7;
    const unsigned rest = idx >> 10;
    const int kt = (int)(rest % (unsigned)ktiles);
    const int nt = (int)(rest / (unsigned)ktiles);
    const int g = lane >> 2, q = lane & 3;
    const int k = kt * 16 + (c & 1) * 8 + q * 2;
    const int n = nt * 128 + (p * 2 + (c >> 1)) * 8 + g;
    out[idx] = __floats2half2_rn(in[(size_t)k * N + n], in[(size_t)(k + 1) * N + n]);
}

__global__ __launch_bounds__(256) void repack_qkvo_kernel(
    const float* __restrict__ Wq, const float* __restrict__ Wk,
    const float* __restrict__ Wv, const float* __restrict__ Wo,
    __half2* __restrict__ wt)
{
    const int z = blockIdx.z, type = z & 3, layer = z >> 2;
    const float* ins[4] = { Wq, Wk, Wv, Wo };
    const float* in = ins[type] + (size_t)layer * HID * HID;
    __half2* out = wt + ((size_t)layer * WT_L + (size_t)type * WT_QKVO) / 2;
    repack_one(in, out, blockIdx.x * 256u + threadIdx.x, HID, HID / 16);
}

__global__ __launch_bounds__(256) void repack_w12_kernel(
    const float* __restrict__ W1, const float* __restrict__ W2,
    __half2* __restrict__ wt)
{
    const int z = blockIdx.z;
    const size_t szF = (size_t)HID * FFN;
    const unsigned idx = blockIdx.x * 256u + threadIdx.x;
    if (z < NLAYER) {
        const float* in = W1 + (size_t)z * szF;
        __half2* out = wt + ((size_t)z * WT_L + 4 * (size_t)WT_QKVO) / 2;
        repack_one(in, out, idx, FFN, HID / 16);
    } else {
        const int layer = z - NLAYER;
        const float* in = W2 + (size_t)layer * szF;
        __half2* out = wt + ((size_t)layer * WT_L + 4 * (size_t)WT_QKVO + szF) / 2;
        repack_one(in, out, idx, HID, FFN / 16);
    }
}

// ---------------------------------------------------------------------------
// fp16 mma.sync GEMM, K-chunk 32, 3-stage cp.async pipeline, 1 sync/iter.
// CTA 128x128, 256 thr (8 warps, 4xM 2xN, warp tile 32x64).
// smem: stA [3][128*40] halves (stride 40 -> conflict-free), fgB [3][512] uint4.
// ---------------------------------------------------------------------------
#define ASTRIDE 40
#define HG_SMEM (3*(128*ASTRIDE*2) + 3*512*16)   // 30720 + 24576 = 55296 B

template<int MODE, bool OUTH, bool QKV>
__global__ __launch_bounds__(256, 2) void hgemm_kernel(
    const __half* __restrict__ A, const __half* __restrict__ Wpk,
    const float* __restrict__ bias0, const float* __restrict__ bias1,
    const float* __restrict__ bias2, const float* __restrict__ R,
    void* __restrict__ C0, void* __restrict__ C1, void* __restrict__ C2,
    int K, int N)
{
    extern __shared__ char hsm[];
    __half* stA = (__half*)hsm;                           // [3][128*40]
    uint4*  fgB = (uint4*)(hsm + 3 * 128 * ASTRIDE * 2);  // [3][512]

    const int tid  = threadIdx.x;
    const int lane = tid & 31;
    const int warp = tid >> 5;
    const int g    = lane >> 2;
    const int q    = lane & 3;
    const int bm0  = blockIdx.y * 128;
    const int wn   = (warp & 1) * 64;
    const int wm   = (warp >> 1) * 32;

    int bn0 = blockIdx.x * 128;
    const float* bias = bias0;
    void* Cout = C0;
    if (QKV) {
        const int type = blockIdx.x / 6;         // 0=q 1=k 2=v
        bn0 -= type * 768;
        bias = (type == 0) ? bias0 : (type == 1 ? bias1 : bias2);
        Cout = (type == 0) ? C0 : (type == 1 ? C1 : C2);
    }

    const int nc = K / 32;
    const __half* Ag = A + (size_t)(bm0 + (tid >> 2)) * K + (tid & 3) * 8;
    const uint4*  Bg = reinterpret_cast<const uint4*>(Wpk)
                       + (size_t)blockIdx.x * (K / 16) * 256 + tid;
    const int saOfs = (tid >> 2) * ASTRIDE + (tid & 3) * 8;

    float acc[2][8][4];
    #pragma unroll
    for (int t = 0; t < 2; t++)
        #pragma unroll
        for (int j = 0; j < 8; j++)
            #pragma unroll
            for (int r = 0; r < 4; r++) acc[t][j][r] = 0.f;

    auto issue = [&](int s, int kt) {
        __half* sa = stA + s * (128 * ASTRIDE);
        cp16(sa + saOfs,                Ag + kt * 32);
        cp16(sa + saOfs + 64 * ASTRIDE, Ag + (size_t)64 * K + kt * 32);
        uint4* fb = fgB + s * 512;
        cp16(fb + tid,       Bg + (size_t)kt * 512);
        cp16(fb + tid + 256, Bg + (size_t)kt * 512 + 256);
        asm volatile("cp.async.commit_group;");
    };

    issue(0, 0); issue(1, 1);

    for (int c = 0; c < nc; c++) {
        if (c < nc - 1) asm volatile("cp.async.wait_group 1;");
        else            asm volatile("cp.async.wait_group 0;");
        __syncthreads();
        if (c + 2 < nc) {
            int s = c + 2; s -= (s >= 3) ? ((s / 3) * 3) : 0;   // (c+2)%3
            issue(s, c + 2);
        }

        int buf = c; buf -= (buf / 3) * 3;                       // c%3
        const __half* sa = stA + buf * (128 * ASTRIDE);
        const uint4*  fb = fgB + buf * 512;

        #pragma unroll
        for (int s = 0; s < 2; s++) {
            unsigned a[2][4];
            #pragma unroll
            for (int t = 0; t < 2; t++) {
                const __half* st = sa + (wm + t * 16 + g) * ASTRIDE + s * 16 + 2 * q;
                a[t][0] = *reinterpret_cast<const unsigned*>(st);
                a[t][1] = *reinterpret_cast<const unsigned*>(st + 8 * ASTRIDE);
                a[t][2] = *reinterpret_cast<const unsigned*>(st + 8);
                a[t][3] = *reinterpret_cast<const unsigned*>(st + 8 * ASTRIDE + 8);
            }
            #pragma unroll
            for (int jp = 0; jp < 4; jp++) {
                const uint4 v = fb[s * 256 + ((warp & 1) * 4 + jp) * 32 + lane];
                mmah(acc[0][jp * 2    ], a[0], v.x, v.y);
                mmah(acc[0][jp * 2 + 1], a[0], v.z, v.w);
                mmah(acc[1][jp * 2    ], a[1], v.x, v.y);
                mmah(acc[1][jp * 2 + 1], a[1], v.z, v.w);
            }
        }
    }

    // epilogue
    #pragma unroll
    for (int t = 0; t < 2; t++) {
        const int m0 = bm0 + wm + t * 16 + g;
        const int m1 = m0 + 8;
        #pragma unroll
        for (int j = 0; j < 8; j++) {
            const int n0 = bn0 + wn + j * 8 + q * 2;
            const float b0 = bias[n0], b1 = bias[n0 + 1];
            float v00 = acc[t][j][0] + b0;
            float v01 = acc[t][j][1] + b1;
            float v10 = acc[t][j][2] + b0;
            float v11 = acc[t][j][3] + b1;
            if (MODE == EP_BIAS_GELU) {
                v00 = 0.5f * v00 * (1.f + erff(v00 * 0.70710678118654752f));
                v01 = 0.5f * v01 * (1.f + erff(v01 * 0.70710678118654752f));
                v10 = 0.5f * v10 * (1.f + erff(v10 * 0.70710678118654752f));
                v11 = 0.5f * v11 * (1.f + erff(v11 * 0.70710678118654752f));
            }
            if (MODE == EP_BIAS_RES) {
                const float2 r0 = *reinterpret_cast<const float2*>(R + (size_t)m0 * N + n0);
                const float2 r1 = *reinterpret_cast<const float2*>(R + (size_t)m1 * N + n0);
                v00 += r0.x; v01 += r0.y; v10 += r1.x; v11 += r1.y;
            }
            if (OUTH) {
                __half2* C = (__half2*)Cout;
                C[((size_t)m0 * N + n0) >> 1] = __floats2half2_rn(v00, v01);
                C[((size_t)m1 * N + n0) >> 1] = __floats2half2_rn(v10, v11);
            } else {
                float* C = (float*)Cout;
                *reinterpret_cast<float2*>(C + (size_t)m0 * N + n0) = make_float2(v00, v01);
                *reinterpret_cast<float2*>(C + (size_t)m1 * N + n0) = make_float2(v10, v11);
            }
        }
    }
}

// ---------------------------------------------------------------------------
// fused: atom-encoder SGEMM (x<6) + structural bias + graph-token fill (x>=6)
// ---------------------------------------------------------------------------
#define BM 128
#define BN 128
#define BK 8
#define TM 8
#define TN 8
#define XTRA 1538u

__global__ __launch_bounds__(256) void atom_fused_kernel(
    const float* __restrict__ A, const float* __restrict__ W,
    const float* __restrict__ bias_b, float* __restrict__ C,
    const int* __restrict__ len_spd, const float* __restrict__ spd_emb,
    const float* __restrict__ virt, const float* __restrict__ gt,
    float* __restrict__ bias)
{
    const int tid = threadIdx.x;

    if (blockIdx.x >= 6) {
        const size_t idx = ((size_t)(blockIdx.x - 6) * 64 + blockIdx.y) * 256 + tid;
        const size_t btot = (size_t)BATCH * NHEAD * NTOT * NTOT;
        if (idx < btot) {
            const int j = (int)(idx & 255);
            const int i = (int)((idx >> 8) & 255);
            const int hh = (int)((idx >> 16) % NHEAD);
            const int b = (int)(idx / ((size_t)NHEAD * NTOT * NTOT));
            float v;
            if (i == 0 || j == 0) {
                v = virt[hh];
            } else {
                const int lsp = len_spd[((size_t)b * NTOK + (i - 1)) * NTOK + (j - 1)];
                v = (lsp == 0) ? 0.f : spd_emb[lsp * NHEAD + hh];
            }
            bias[idx] = v;
        } else {
            const size_t r = idx - btot;
            if (r < (size_t)BATCH * HID) {
                const int b = (int)(r / HID), t = (int)(r % HID);
                C[(size_t)b * NTOT * HID + t] = gt[t];
            }
        }
        return;
    }

    __shared__ float As[BK][BM];
    __shared__ float Bs[BK][BN];

    const int bm0 = blockIdx.y * BM;
    const int bn0 = blockIdx.x * BN;
    const int tx = tid & 15;
    const int ty = tid >> 4;

    float acc[TM][TN];
    #pragma unroll
    for (int i = 0; i < TM; i++)
        #pragma unroll
        for (int j = 0; j < TN; j++) acc[i][j] = 0.f;

    const int arow = tid >> 1;
    const int acol = (tid & 1) * 4;
    const int brow = tid >> 5;
    const int bcol = (tid & 31) * 4;

    for (int k0 = 0; k0 < DIN; k0 += BK) {
        float4 av;
        const int gm = bm0 + arow;
        if (gm < MATOM)
            av = *reinterpret_cast<const float4*>(A + (size_t)gm * DIN + k0 + acol);
        else
            av = make_float4(0.f, 0.f, 0.f, 0.f);
        As[acol + 0][arow] = av.x;
        As[acol + 1][arow] = av.y;
        As[acol + 2][arow] = av.z;
        As[acol + 3][arow] = av.w;

        const float4 bv = *reinterpret_cast<const float4*>(
            W + (size_t)(k0 + brow) * HID + bn0 + bcol);
        *reinterpret_cast<float4*>(&Bs[brow][bcol]) = bv;

        __syncthreads();
        #pragma unroll
        for (int k = 0; k < BK; k++) {
            float af[TM], bf[TN];
            #pragma unroll
            for (int i = 0; i < TM; i++) af[i] = As[k][ty * TM + i];
            #pragma unroll
            for (int j = 0; j < TN; j++) bf[j] = Bs[k][tx * TN + j];
            #pragma unroll
            for (int i = 0; i < TM; i++)
                #pragma unroll
                for (int j = 0; j < TN; j++)
                    acc[i][j] = fmaf(af[i], bf[j], acc[i][j]);
        }
        __syncthreads();
    }

    #pragma unroll
    for (int i = 0; i < TM; i++) {
        const int m = bm0 + ty * TM + i;
        if (m >= MATOM) continue;
        const size_t orow = (size_t)m + (size_t)(m / NTOK) + 1;
        #pragma unroll
        for (int j = 0; j < TN; j++) {
            const int nn = bn0 + tx * TN + j;
            C[orow * HID + nn] = acc[i][j] + bias_b[nn];
        }
    }
}

// ---------------------------------------------------------------------------
// LayerNorm (templated output dtype)
// ---------------------------------------------------------------------------
template<bool OUTH>
__global__ __launch_bounds__(256) void ln_kernel(
    const float* __restrict__ X, const float* __restrict__ w,
    const float* __restrict__ b, void* __restrict__ Yout)
{
    const int row = blockIdx.x;
    const float* x = X + (size_t)row * HID;
    const int tid = threadIdx.x;

    float v0 = x[tid], v1 = x[tid + 256], v2 = x[tid + 512];
    float s = v0 + v1 + v2;

    __shared__ float red[8];
    #pragma unroll
    for (int o = 16; o > 0; o >>= 1) s += __shfl_xor_sync(~0u, s, o);
    if ((tid & 31) == 0) red[tid >> 5] = s;
    __syncthreads();
    float tot = red[0];
    #pragma unroll
    for (int wv = 1; wv < 8; wv++) tot += red[wv];
    const float mu = tot * (1.f / HID);
    __syncthreads();

    const float d0 = v0 - mu, d1 = v1 - mu, d2 = v2 - mu;
    float s2 = d0 * d0 + d1 * d1 + d2 * d2;
    #pragma unroll
    for (int o = 16; o > 0; o >>= 1) s2 += __shfl_xor_sync(~0u, s2, o);
    if ((tid & 31) == 0) red[tid >> 5] = s2;
    __syncthreads();
    float var = red[0];
    #pragma unroll
    for (int wv = 1; wv < 8; wv++) var += red[wv];
    var *= (1.f / HID);
    const float inv = rsqrtf(var + 1e-5f);

    const float y0 = d0 * inv * w[tid]       + b[tid];
    const float y1 = d1 * inv * w[tid + 256] + b[tid + 256];
    const float y2 = d2 * inv * w[tid + 512] + b[tid + 512];
    if (OUTH) {
        __half* Y = (__half*)Yout + (size_t)row * HID;
        Y[tid]       = __float2half_rn(y0);
        Y[tid + 256] = __float2half_rn(y1);
        Y[tid + 512] = __float2half_rn(y2);
    } else {
        float* Y = (float*)Yout + (size_t)row * HID;
        Y[tid] = y0; Y[tid + 256] = y1; Y[tid + 512] = y2;
    }
}

// ---------------------------------------------------------------------------
// Attention v3: tensor-core MMA (unchanged from R11)
// ---------------------------------------------------------------------------
#define KT_S 264
#define VT_S 72
#define QS_S 36
#define ATTN_SMEM ((32*KT_S + 128*VT_S + 128*QS_S) * 4)

__global__ __launch_bounds__(256, 1) void attn_kernel(
    const __half* __restrict__ Q, const __half* __restrict__ K,
    const __half* __restrict__ V, const float* __restrict__ bias,
    __half* __restrict__ O)
{
    extern __shared__ char smraw[];
    __half2* KT = (__half2*)smraw;
    __half2* VT = KT + 32 * KT_S;
    __half2* QS = VT + 128 * VT_S;

    const int h = blockIdx.x, b = blockIdx.y;
    const int tid = threadIdx.x, lane = tid & 31, warp = tid >> 5;
    const int g = lane >> 2, q = lane & 3;
    const size_t base = (size_t)b * NTOT * HID + (size_t)h * HDIM;

    for (int i = tid; i < 8192; i += 256) {
        const int n = i >> 5, k2 = i & 31;
        KT[k2 * KT_S + n] =
            reinterpret_cast<const __half2*>(K + base + (size_t)n * HID)[k2];
    }
    for (int i = tid; i < 8192; i += 256) {
        const int t2 = i >> 6, d = i & 63;
        VT[t2 * VT_S + d] = __halves2half2(V[base + (size_t)(2 * t2) * HID + d],
                                           V[base + (size_t)(2 * t2 + 1) * HID + d]);
    }

    const float* bb = bias + (((size_t)b * NHEAD + h) * NTOT) * NTOT;

    for (int pass = 0; pass < 2; pass++) {
        __syncthreads();
        for (int i = tid; i < 4096; i += 256) {
            const int r = i >> 5, k2 = i & 31;
            QS[r * QS_S + k2] = reinterpret_cast<const __half2*>(
                Q + base + (size_t)(pass * 128 + r) * HID)[k2];
        }
        __syncthreads();

        const int r0 = warp * 16;
        float sc[32][4];
        #pragma unroll
        for (int j = 0; j < 32; j++) {
            sc[j][0] = sc[j][1] = sc[j][2] = sc[j][3] = 0.f;
        }

        #pragma unroll
        for (int kt = 0; kt < 4; kt++) {
            unsigned a[4];
            a[0] = *reinterpret_cast<const unsigned*>(&QS[(r0 + g    ) * QS_S + q + 8 * kt]);
            a[1] = *reinterpret_cast<const unsigned*>(&QS[(r0 + g + 8) * QS_S + q + 8 * kt]);
            a[2] = *reinterpret_cast<const unsigned*>(&QS[(r0 + g    ) * QS_S + q + 4 + 8 * kt]);
            a[3] = *reinterpret_cast<const unsigned*>(&QS[(r0 + g + 8) * QS_S + q + 4 + 8 * kt]);
            #pragma unroll
            for (int j = 0; j < 32; j++) {
                const unsigned b0 = *reinterpret_cast<const unsigned*>(
                    &KT[(8 * kt + q    ) * KT_S + j * 8 + g]);
                const unsigned b1 = *reinterpret_cast<const unsigned*>(
                    &KT[(8 * kt + 4 + q) * KT_S + j * 8 + g]);
                mmah(sc[j], a, b0, b1);
            }
        }

        const int qi0 = pass * 128 + r0 + g;
        const int qi1 = qi0 + 8;
        const float* b0r = bb + (size_t)qi0 * NTOT;
        const float* b1r = bb + (size_t)qi1 * NTOT;

        float m0 = -1e30f, m1 = -1e30f;
        #pragma unroll
        for (int j = 0; j < 32; j++) {
            const float2 bg0 = *reinterpret_cast<const float2*>(&b0r[j * 8 + 2 * q]);
            const float2 bg1 = *reinterpret_cast<const float2*>(&b1r[j * 8 + 2 * q]);
            sc[j][0] = sc[j][0] * 0.125f + bg0.x;
            sc[j][1] = sc[j][1] * 0.125f + bg0.y;
            sc[j][2] = sc[j][2] * 0.125f + bg1.x;
            sc[j][3] = sc[j][3] * 0.125f + bg1.y;
            m0 = fmaxf(m0, fmaxf(sc[j][0], sc[j][1]));
            m1 = fmaxf(m1, fmaxf(sc[j][2], sc[j][3]));
        }
        m0 = fmaxf(m0, __shfl_xor_sync(~0u, m0, 1));
        m0 = fmaxf(m0, __shfl_xor_sync(~0u, m0, 2));
        m1 = fmaxf(m1, __shfl_xor_sync(~0u, m1, 1));
        m1 = fmaxf(m1, __shfl_xor_sync(~0u, m1, 2));

        float s0 = 0.f, s1 = 0.f;
        unsigned p0[32], p1[32];
        #pragma unroll
        for (int j = 0; j < 32; j++) {
            const float e0 = expf(sc[j][0] - m0), e1 = expf(sc[j][1] - m0);
            const float e2 = expf(sc[j][2] - m1), e3 = expf(sc[j][3] - m1);
            s0 += e0 + e1; s1 += e2 + e3;
            const __half2 h0 = __floats2half2_rn(e0, e1);
            const __half2 h1 = __floats2half2_rn(e2, e3);
            p0[j] = *reinterpret_cast<const unsigned*>(&h0);
            p1[j] = *reinterpret_cast<const unsigned*>(&h1);
        }
        s0 += __shfl_xor_sync(~0u, s0, 1); s0 += __shfl_xor_sync(~0u, s0, 2);
        s1 += __shfl_xor_sync(~0u, s1, 1); s1 += __shfl_xor_sync(~0u, s1, 2);
        const float i0 = 1.f / s0, i1 = 1.f / s1;

        float av[8][4];
        #pragma unroll
        for (int j = 0; j < 8; j++) {
            av[j][0] = av[j][1] = av[j][2] = av[j][3] = 0.f;
        }
        #pragma unroll
        for (int kt = 0; kt < 16; kt++) {
            const unsigned a[4] = { p0[2 * kt], p1[2 * kt], p0[2 * kt + 1], p1[2 * kt + 1] };
            #pragma unroll
            for (int j = 0; j < 8; j++) {
                const unsigned vb0 = *reinterpret_cast<const unsigned*>(
                    &VT[(8 * kt + q    ) * VT_S + j * 8 + g]);
                const unsigned vb1 = *reinterpret_cast<const unsigned*>(
                    &VT[(8 * kt + 4 + q) * VT_S + j * 8 + g]);
                mmah(av[j], a, vb0, vb1);
            }
        }

        __half2* O0 = reinterpret_cast<__half2*>(O + base + (size_t)qi0 * HID);
        __half2* O1 = reinterpret_cast<__half2*>(O + base + (size_t)qi1 * HID);
        #pragma unroll
        for (int j = 0; j < 8; j++) {
            O0[j * 4 + q] = __floats2half2_rn(av[j][0] * i0, av[j][1] * i0);
            O1[j * 4 + q] = __floats2half2_rn(av[j][2] * i1, av[j][3] * i1);
        }
    }
}

// ---------------------------------------------------------------------------
// Launch
// ---------------------------------------------------------------------------
extern "C" void kernel_launch(void* const* d_in, const int* in_sizes, int n_in,
                              void* d_out, int out_size)
{
    const float* x          = (const float*)d_in[0];
    const int*   len_spd    = (const int*)  d_in[1];
    const float* atom_W     = (const float*)d_in[2];
    const float* atom_b     = (const float*)d_in[3];
    const float* spd_emb    = (const float*)d_in[4];
    const float* graph_tok  = (const float*)d_in[5];
    const float* virt_dist  = (const float*)d_in[6];
    const float* ln1_w      = (const float*)d_in[7];
    const float* ln1_b      = (const float*)d_in[8];
    const float* Wq         = (const float*)d_in[9];
    const float* bq         = (const float*)d_in[10];
    const float* Wk         = (const float*)d_in[11];
    const float* bk         = (const float*)d_in[12];
    const float* Wv         = (const float*)d_in[13];
    const float* bv         = (const float*)d_in[14];
    const float* Wo         = (const float*)d_in[15];
    const float* bo         = (const float*)d_in[16];
    const float* ln2_w      = (const float*)d_in[17];
    const float* ln2_b      = (const float*)d_in[18];
    const float* W1         = (const float*)d_in[19];
    const float* b1         = (const float*)d_in[20];
    const float* W2         = (const float*)d_in[21];
    const float* b2         = (const float*)d_in[22];
    const float* fln_w      = (const float*)d_in[23];
    const float* fln_b      = (const float*)d_in[24];

    float *h, *bias;
    __half *yh, *qh, *kh, *vh, *oh, *fh, *wt;
    cudaGetSymbolAddress((void**)&h,    g_h);
    cudaGetSymbolAddress((void**)&yh,   g_yh);
    cudaGetSymbolAddress((void**)&qh,   g_qh);
    cudaGetSymbolAddress((void**)&kh,   g_kh);
    cudaGetSymbolAddress((void**)&vh,   g_vh);
    cudaGetSymbolAddress((void**)&oh,   g_oh);
    cudaGetSymbolAddress((void**)&fh,   g_fh);
    cudaGetSymbolAddress((void**)&bias, g_bias);
    cudaGetSymbolAddress((void**)&wt,   g_wt);

    cudaFuncSetAttribute(attn_kernel, cudaFuncAttributeMaxDynamicSharedMemorySize,
                         (int)ATTN_SMEM);
    cudaFuncSetAttribute(hgemm_kernel<EP_BIAS, true, true>,
                         cudaFuncAttributeMaxDynamicSharedMemorySize, HG_SMEM);
    cudaFuncSetAttribute(hgemm_kernel<EP_BIAS_RES, false, false>,
                         cudaFuncAttributeMaxDynamicSharedMemorySize, HG_SMEM);
    cudaFuncSetAttribute(hgemm_kernel<EP_BIAS_GELU, true, false>,
                         cudaFuncAttributeMaxDynamicSharedMemorySize, HG_SMEM);

    const size_t szQ = (size_t)HID * HID, szF = (size_t)HID * FFN;

    const dim3 gQKV(18, MROWS / 128);
    const dim3 gHID(HID / 128, MROWS / 128);
    const dim3 gFFN(FFN / 128, MROWS / 128);

    // L1: repack QKVO weights (all layers)
    repack_qkvo_kernel<<<dim3((unsigned)(szQ / 2 / 256), 1, 4 * NLAYER), 256>>>(
        Wq, Wk, Wv, Wo, (__half2*)wt);
    // L2: fused atom encoder + bias + token fill
    atom_fused_kernel<<<dim3(6 + XTRA, 64), 256>>>(
        x, atom_W, atom_b, h, len_spd, spd_emb, virt_dist, graph_tok, bias);
    // L3: ln1 layer 0
    ln_kernel<true><<<MROWS, 256>>>(h, ln1_w, ln1_b, yh);
    // L4: QKV fused hgemm layer 0  <-- ncu capture slot
    hgemm_kernel<EP_BIAS, true, true><<<gQKV, 256, HG_SMEM>>>(
        yh, wt, bq, bk, bv, nullptr, qh, kh, vh, HID, HID);
    // L5: repack W1/W2
    repack_w12_kernel<<<dim3((unsigned)(szF / 2 / 256), 1, 2 * NLAYER), 256>>>(
        W1, W2, (__half2*)wt);

    for (int l = 0; l < NLAYER; l++) {
        const size_t bofs  = (size_t)l * HID;
        const size_t b1ofs = (size_t)l * FFN;
        __half* wl = wt + (size_t)l * WT_L;

        if (l > 0) {
            ln_kernel<true><<<MROWS, 256>>>(h, ln1_w + bofs, ln1_b + bofs, yh);
            hgemm_kernel<EP_BIAS, true, true><<<gQKV, 256, HG_SMEM>>>(
                yh, wl, bq + bofs, bk + bofs, bv + bofs, nullptr,
                qh, kh, vh, HID, HID);
        }

        attn_kernel<<<dim3(NHEAD, BATCH), 256, ATTN_SMEM>>>(qh, kh, vh, bias, oh);

        hgemm_kernel<EP_BIAS_RES, false, false><<<gHID, 256, HG_SMEM>>>(
            oh, wl + 3 * (size_t)WT_QKVO, bo + bofs, nullptr, nullptr, h,
            h, nullptr, nullptr, HID, HID);

        ln_kernel<true><<<MROWS, 256>>>(h, ln2_w + bofs, ln2_b + bofs, yh);

        hgemm_kernel<EP_BIAS_GELU, true, false><<<gFFN, 256, HG_SMEM>>>(
            yh, wl + 4 * (size_t)WT_QKVO, b1 + b1ofs, nullptr, nullptr, nullptr,
            fh, nullptr, nullptr, HID, FFN);
        hgemm_kernel<EP_BIAS_RES, false, false><<<gHID, 256, HG_SMEM>>>(
            fh, wl + 4 * (size_t)WT_QKVO + szF, b2 + bofs, nullptr, nullptr, h,
            h, nullptr, nullptr, FFN, HID);
    }

    ln_kernel<false><<<MROWS, 256>>>(h, fln_w, fln_b, d_out);
}